// round 2
// baseline (speedup 1.0000x reference)
#include <cuda_runtime.h>
#include <math.h>

#define N 4096
#define D 128
#define KK 4
#define BM 64
#define BN 64
#define NBJ (N / BN)   // 64 column-blocks
#define EPSF 1e-6f

// Partials: one slot per (row, stat, column-block). Written exactly once each
// by tile_kernel, so no zero-init needed. stats: [c,S1,S2,NA,NB,NC,U1,UA,U2]
__device__ float g_part[N * 9 * NBJ];
__device__ float g_rowloss[N];
__device__ int   g_estride;   // labels element stride in ints: 1 (int32) or 2 (int64)

// Detect labels memory layout. Labels are values in [0,64). If stored as
// little-endian int64, every odd int word is a zero high-word. If stored as
// int32, odd words are live label values (all-zero has probability ~64^-8192).
__global__ void detect_kernel(const int* __restrict__ labels) {
    __shared__ int any;
    if (threadIdx.x == 0) any = 0;
    __syncthreads();
    int f = 0;
    for (int idx = 1 + 2 * threadIdx.x; idx < N * KK; idx += 2 * blockDim.x)
        if (labels[idx] != 0) f = 1;
    if (f) any = 1;
    __syncthreads();
    if (threadIdx.x == 0) g_estride = any ? 1 : 2;
}

// Dynamic smem: float4 Xa[64*32] (32KB) | float4 Xb[64*32] (32KB) |
//               float4 tbl[16] | int sTi[64] | int4 sLab[64]
#define SMEM_BYTES (64*32*16 * 2 + 256 + 256 + 1024)

__global__ __launch_bounds__(256) void tile_kernel(
    const float* __restrict__ X,
    const int* __restrict__ labels,
    float a0, float a1, float a2, float a3)
{
    extern __shared__ char smem[];
    float4* Xa  = (float4*)smem;
    float4* Xb  = Xa + 64 * 32;
    float4* tbl = Xb + 64 * 32;
    int*    sTi = (int*)(tbl + 16);
    int4*  sLab = (int4*)(sTi + 64);

    const int tid = threadIdx.x;
    const int bi = blockIdx.y, bj = blockIdx.x;
    const int ibase = bi * BM, jbase = bj * BN;
    const int es = g_estride;

    // ---- load X tiles, k-major with XOR swizzle: slot = row*32 + (k4 ^ (row&31))
    const float4* Xg = (const float4*)X;   // X: [4096][128] -> [4096][32] float4
    #pragma unroll
    for (int it = 0; it < 8; it++) {
        int fidx = tid + it * 256;
        int row  = fidx >> 5;
        int k4   = fidx & 31;
        int slot = row * 32 + (k4 ^ (row & 31));
        Xa[slot] = Xg[(ibase + row) * 32 + k4];
        Xb[slot] = Xg[(jbase + row) * 32 + k4];
    }

    // ---- labels + neg-pattern table
    if (tid < 64) {
        sTi[tid] = labels[((ibase + tid) * KK) * es];     // labels[i][0]
        int j = jbase + tid;
        int4 lb;
        lb.x = labels[(j * KK + 0) * es];
        lb.y = labels[(j * KK + 1) * es];
        lb.z = labels[(j * KK + 2) * es];
        lb.w = labels[(j * KK + 3) * es];
        sLab[tid] = lb;
    } else if (tid < 80) {
        int eb = tid - 64;
        int e0 = eb & 1, e1 = (eb >> 1) & 1, e2 = (eb >> 2) & 1, e3 = (eb >> 3) & 1;
        // neg_m: m0=!e3, m1=!e2&e3, m2=!e1&e2, m3=!e0&e1
        int n0 = !e3;
        int n1 = (!e2) & e3;
        int n2 = (!e1) & e2;
        int n3 = (!e0) & e1;
        float k   = (float)(n0 + n1 + n2 + n3);
        float sa  = n0 * a0 + n1 * a1 + n2 * a2 + n3 * a3;
        float sa2 = n0 * a0 * a0 + n1 * a1 * a1 + n2 * a2 * a2 + n3 * a3 * a3;
        tbl[eb] = make_float4(k, sa, sa2, 0.0f);
    }
    __syncthreads();

    const int tx = tid & 15, ty = tid >> 4;
    const int rb = ty * 4, cb = tx * 4;

    float acc[4][4] = {};

    // ---- GEMM mainloop
    #pragma unroll 8
    for (int k4 = 0; k4 < 32; k4++) {
        float4 av[4], bv[4];
        #pragma unroll
        for (int q = 0; q < 4; q++) {
            int r = rb + q;
            av[q] = Xa[r * 32 + (k4 ^ (r & 31))];
            int c = cb + q;
            bv[q] = Xb[c * 32 + (k4 ^ (c & 31))];
        }
        #pragma unroll
        for (int r = 0; r < 4; r++)
            #pragma unroll
            for (int c = 0; c < 4; c++) {
                acc[r][c] += av[r].x * bv[c].x;
                acc[r][c] += av[r].y * bv[c].y;
                acc[r][c] += av[r].z * bv[c].z;
                acc[r][c] += av[r].w * bv[c].w;
            }
    }

    // ---- epilogue: per-pair log + mask stats; reduce per row immediately
    int4 lb[4];
    #pragma unroll
    for (int c = 0; c < 4; c++) lb[c] = sLab[cb + c];

    #pragma unroll
    for (int r = 0; r < 4; r++) {
        float st[9];
        #pragma unroll
        for (int s = 0; s < 9; s++) st[s] = 0.0f;

        const int t  = sTi[rb + r];
        const int gi = ibase + rb + r;
        #pragma unroll
        for (int c = 0; c < 4; c++) {
            float L  = __logf(acc[r][c] + EPSF);
            float L2 = L * L;
            int e0 = (t == lb[c].x);
            int eb = e0 | ((t == lb[c].y) << 1) | ((t == lb[c].z) << 2) | ((t == lb[c].w) << 3);
            float4 tv = tbl[eb];
            st[3] += tv.x;                     // NA
            st[4] += tv.y;                     // NB
            st[5] += tv.z;                     // NC
            st[6] = fmaf(tv.x, L,  st[6]);     // U1
            st[7] = fmaf(tv.y, L,  st[7]);     // UA
            st[8] = fmaf(tv.x, L2, st[8]);     // U2
            int gj = jbase + cb + c;
            if (e0 && (gi != gj)) {
                st[0] += 1.0f;                 // c
                st[1] += L;                    // S1
                st[2] += L2;                   // S2
            }
        }

        // reduce across 16 tx threads sharing this row (stays within half-warp)
        #pragma unroll
        for (int s = 0; s < 9; s++) {
            float v = st[s];
            v += __shfl_xor_sync(0xffffffffu, v, 8);
            v += __shfl_xor_sync(0xffffffffu, v, 4);
            v += __shfl_xor_sync(0xffffffffu, v, 2);
            v += __shfl_xor_sync(0xffffffffu, v, 1);
            if (tx == 0) g_part[(gi * 9 + s) * NBJ + bj] = v;   // written exactly once
        }
    }
}

// Per-row combine: deterministic fixed-order sum over the 64 column-blocks.
__global__ void combine1_kernel() {
    int i = blockIdx.x * blockDim.x + threadIdx.x;
    if (i >= N) return;
    float agg[9];
    #pragma unroll
    for (int s = 0; s < 9; s++) {
        const float4* p = (const float4*)&g_part[(i * 9 + s) * NBJ];
        float sum = 0.0f;
        #pragma unroll
        for (int q = 0; q < NBJ / 4; q++) {
            float4 t = p[q];
            sum += t.x + t.y + t.z + t.w;
        }
        agg[s] = sum;
    }
    float c  = agg[0], S1 = agg[1], S2 = agg[2];
    float NA = agg[3], NB = agg[4], NC = agg[5];
    float U1 = agg[6], UA = agg[7], U2 = agg[8];
    g_rowloss[i] = S2 * NA - 2.0f * S1 * (U1 + NB) + c * (U2 + 2.0f * UA + NC);
}

// Final scalar: single block, fixed-order tree -> deterministic output.
__global__ void combine2_kernel(float* __restrict__ out) {
    __shared__ float sh[256];
    float v = 0.0f;
    for (int i = threadIdx.x; i < N; i += 256) v += g_rowloss[i];
    sh[threadIdx.x] = v;
    __syncthreads();
    for (int o = 128; o; o >>= 1) {
        if (threadIdx.x < o) sh[threadIdx.x] += sh[threadIdx.x + o];
        __syncthreads();
    }
    if (threadIdx.x == 0) out[0] = sh[0];
}

extern "C" void kernel_launch(void* const* d_in, const int* in_sizes, int n_in,
                              void* d_out, int out_size) {
    (void)in_sizes; (void)n_in; (void)out_size;
    const float* X      = (const float*)d_in[0];
    const int*   labels = (const int*)d_in[1];
    float*       out    = (float*)d_out;

    // a_m = 0.1 * (log(omega+eps) - log(omega^(5-m)+eps)), double precision on host
    const double lg = log(0.1 + 1e-6);
    float a[4];
    for (int m = 0; m < 4; m++)
        a[m] = (float)(0.1 * (lg - log(pow(0.1, (double)(5 - m)) + 1e-6)));

    cudaFuncSetAttribute(tile_kernel, cudaFuncAttributeMaxDynamicSharedMemorySize, SMEM_BYTES);

    detect_kernel<<<1, 256>>>(labels);
    dim3 grid(N / BN, N / BM);
    tile_kernel<<<grid, 256, SMEM_BYTES>>>(X, labels, a[0], a[1], a[2], a[3]);
    combine1_kernel<<<N / 256, 256>>>();
    combine2_kernel<<<1, 256>>>(out);
}

// round 7
// speedup vs baseline: 3.3839x; 3.3839x over previous
#include <cuda_runtime.h>
#include <cuda_bf16.h>
#include <cstdint>
#include <math.h>

typedef unsigned int u32;

#define N 4096
#define KK 4
#define TS 128
#define NBJ (N / TS)
#define EPSF 1e-6f

__device__ float g_part[N * 9 * NBJ];
__device__ float g_bsum[16];
__device__ int   g_estride;

__device__ __forceinline__ u32 smem_u32(const void* p) {
    u32 a;
    asm("{ .reg .u64 t; cvta.to.shared.u64 t, %1; cvt.u32.u64 %0, t; }" : "=r"(a) : "l"(p));
    return a;
}

__device__ __forceinline__ void ldsm_x4(u32* r, u32 addr) {
    asm volatile("ldmatrix.sync.aligned.m8n8.x4.shared.b16 {%0,%1,%2,%3}, [%4];"
                 : "=r"(r[0]), "=r"(r[1]), "=r"(r[2]), "=r"(r[3]) : "r"(addr));
}

__device__ __forceinline__ void ldsm_x2(u32* r, u32 addr) {
    asm volatile("ldmatrix.sync.aligned.m8n8.x2.shared.b16 {%0,%1}, [%2];"
                 : "=r"(r[0]), "=r"(r[1]) : "r"(addr));
}

__device__ __forceinline__ void mma_bf16(float* c, const u32* a, const u32* b) {
    asm volatile(
        "mma.sync.aligned.m16n8k16.row.col.f32.bf16.bf16.f32 "
        "{%0,%1,%2,%3}, {%4,%5,%6,%7}, {%8,%9}, {%0,%1,%2,%3};"
        : "+f"(c[0]), "+f"(c[1]), "+f"(c[2]), "+f"(c[3])
        : "r"(a[0]), "r"(a[1]), "r"(a[2]), "r"(a[3]), "r"(b[0]), "r"(b[1]));
}

#define OFF_AHI   0
#define OFF_ALO   32768
#define OFF_BHI   65536
#define OFF_BLO   98304
#define OFF_TBL   131072
#define OFF_STI   131328
#define OFF_SLAB  131840
#define SMEM_BYTES 133888

// Tile row layout: 128 rows x 256 bytes (128 bf16). 16B blocks XOR-swizzled:
// phys = row*256 + ((c16 ^ (row & 7)) << 4)
__device__ __forceinline__ int sw_addr(int row, int c16) {
    return row * 256 + ((c16 ^ (row & 7)) << 4);
}

__global__ void detect_kernel(const int* __restrict__ labels) {
    __shared__ int any;
    if (threadIdx.x == 0) any = 0;
    __syncthreads();
    int f = 0;
    for (int idx = 1 + 2 * threadIdx.x; idx < N * KK; idx += 2 * blockDim.x) {
        if (labels[idx] != 0) f = 1;
    }
    if (f) any = 1;
    __syncthreads();
    if (threadIdx.x == 0) g_estride = (any != 0) ? 1 : 2;
}

__global__ __launch_bounds__(256) void tile_kernel(
    const float* __restrict__ X,
    const int* __restrict__ labels,
    float a0, float a1, float a2, float a3)
{
    extern __shared__ char smem[];
    const u32 sbase = smem_u32(smem);
    float4* tbl = (float4*)(smem + OFF_TBL);
    int* sTi = (int*)(smem + OFF_STI);
    int4* sLab = (int4*)(smem + OFF_SLAB);

    const int tid = threadIdx.x;
    const int lane = tid & 31;
    const int wid = tid >> 5;
    const int wr = wid >> 2;
    const int wc = wid & 3;
    const int ibase = blockIdx.y * TS;
    const int jbase = blockIdx.x * TS;
    const int es = g_estride;

    // ---- load X tiles, split fp32 -> bf16 hi/lo, store swizzled ----
    const float4* Xg = (const float4*)X;   // X: [4096][32] float4
    #pragma unroll
    for (int it = 0; it < 16; it++) {
        int idx = tid + it * 256;          // 0..4095
        int row = idx >> 5;
        int c8 = idx & 31;                 // 8-byte-bf16 unit == float4 unit
        int off = sw_addr(row, c8 >> 1) + (c8 & 1) * 8;
        float4 va = Xg[(ibase + row) * 32 + c8];
        float4 vb = Xg[(jbase + row) * 32 + c8];
        #pragma unroll
        for (int t2 = 0; t2 < 2; t2++) {
            float4 v = (t2 != 0) ? vb : va;
            unsigned hx = (unsigned)__bfloat16_as_ushort(__float2bfloat16(v.x));
            unsigned hy = (unsigned)__bfloat16_as_ushort(__float2bfloat16(v.y));
            unsigned hz = (unsigned)__bfloat16_as_ushort(__float2bfloat16(v.z));
            unsigned hw = (unsigned)__bfloat16_as_ushort(__float2bfloat16(v.w));
            float lx = v.x - __bfloat162float(__ushort_as_bfloat16((unsigned short)hx));
            float ly = v.y - __bfloat162float(__ushort_as_bfloat16((unsigned short)hy));
            float lz = v.z - __bfloat162float(__ushort_as_bfloat16((unsigned short)hz));
            float lw = v.w - __bfloat162float(__ushort_as_bfloat16((unsigned short)hw));
            uint2 hv;
            hv.x = hx | (hy << 16);
            hv.y = hz | (hw << 16);
            uint2 lv;
            lv.x = (unsigned)__bfloat16_as_ushort(__float2bfloat16(lx)) |
                   ((unsigned)__bfloat16_as_ushort(__float2bfloat16(ly)) << 16);
            lv.y = (unsigned)__bfloat16_as_ushort(__float2bfloat16(lz)) |
                   ((unsigned)__bfloat16_as_ushort(__float2bfloat16(lw)) << 16);
            int hofs = (t2 != 0) ? OFF_BHI : OFF_AHI;
            int lofs = (t2 != 0) ? OFF_BLO : OFF_ALO;
            *(uint2*)(smem + hofs + off) = hv;
            *(uint2*)(smem + lofs + off) = lv;
        }
    }

    // ---- labels + neg-pattern table ----
    if (tid < 128) {
        sTi[tid] = labels[((ibase + tid) * KK) * es];
        int j = jbase + tid;
        int4 lv4;
        lv4.x = labels[(j * KK + 0) * es];
        lv4.y = labels[(j * KK + 1) * es];
        lv4.z = labels[(j * KK + 2) * es];
        lv4.w = labels[(j * KK + 3) * es];
        sLab[tid] = lv4;
    } else if (tid < 144) {
        int eb = tid - 128;
        int e0 = eb & 1;
        int e1 = (eb >> 1) & 1;
        int e2 = (eb >> 2) & 1;
        int e3 = (eb >> 3) & 1;
        int n0 = 1 - e3;
        int n1 = (1 - e2) & e3;
        int n2 = (1 - e1) & e2;
        int n3 = (1 - e0) & e1;
        float kcnt = (float)(n0 + n1 + n2 + n3);
        float sa = n0 * a0 + n1 * a1 + n2 * a2 + n3 * a3;
        float sa2 = n0 * a0 * a0 + n1 * a1 * a1 + n2 * a2 * a2 + n3 * a3 * a3;
        tbl[eb] = make_float4(kcnt, sa, sa2, 0.0f);
    }
    __syncthreads();

    // ---- GEMM mainloop: hi*hi + hi*lo + lo*hi via mma.sync bf16 ----
    float acc[4][4][4];
    #pragma unroll
    for (int mt = 0; mt < 4; mt++)
        #pragma unroll
        for (int nt = 0; nt < 4; nt++)
            #pragma unroll
            for (int q = 0; q < 4; q++)
                acc[mt][nt][q] = 0.0f;

    const int a_row = lane & 15;
    const int a_k = lane >> 4;
    const int b_row = lane & 7;
    const int b_k = (lane >> 3) & 1;

    #pragma unroll
    for (int ks = 0; ks < 8; ks++) {
        u32 bh[4][2];
        u32 bl[4][2];
        int c16b = ks * 2 + b_k;
        #pragma unroll
        for (int nt = 0; nt < 4; nt++) {
            int r = wc * 32 + nt * 8 + b_row;
            u32 ad = (u32)sw_addr(r, c16b);
            ldsm_x2(bh[nt], sbase + OFF_BHI + ad);
            ldsm_x2(bl[nt], sbase + OFF_BLO + ad);
        }
        int c16a = ks * 2 + a_k;
        #pragma unroll
        for (int mt = 0; mt < 4; mt++) {
            int r = wr * 64 + mt * 16 + a_row;
            u32 ad = (u32)sw_addr(r, c16a);
            u32 ah[4];
            u32 al[4];
            ldsm_x4(ah, sbase + OFF_AHI + ad);
            ldsm_x4(al, sbase + OFF_ALO + ad);
            #pragma unroll
            for (int nt = 0; nt < 4; nt++) {
                mma_bf16(acc[mt][nt], ah, bh[nt]);
                mma_bf16(acc[mt][nt], ah, bl[nt]);
                mma_bf16(acc[mt][nt], al, bh[nt]);
            }
        }
    }

    __syncthreads();   // before overwriting Ahi region with reduce scratch

    // ---- epilogue: per-pair log + mask stats, quad reduce, smem combine ----
    float* sred = (float*)smem;   // [128 rows][4 wc][9]
    #pragma unroll
    for (int mt = 0; mt < 4; mt++) {
        #pragma unroll
        for (int h = 0; h < 2; h++) {
            int row = wr * 64 + mt * 16 + (lane >> 2) + h * 8;
            int gi = ibase + row;
            int tlab = sTi[row];
            float st[9];
            #pragma unroll
            for (int s = 0; s < 9; s++) st[s] = 0.0f;
            #pragma unroll
            for (int nt = 0; nt < 4; nt++) {
                #pragma unroll
                for (int e = 0; e < 2; e++) {
                    float v = acc[mt][nt][h * 2 + e];
                    int col = wc * 32 + nt * 8 + ((lane & 3) << 1) + e;
                    float L = __logf(v + EPSF);
                    float L2 = L * L;
                    int4 lbv = sLab[col];
                    int p0 = (tlab == lbv.x) ? 1 : 0;
                    int eb = p0 | (((tlab == lbv.y) ? 1 : 0) << 1) |
                             (((tlab == lbv.z) ? 1 : 0) << 2) |
                             (((tlab == lbv.w) ? 1 : 0) << 3);
                    float4 tv = tbl[eb];
                    st[3] += tv.x;
                    st[4] += tv.y;
                    st[5] += tv.z;
                    st[6] = fmaf(tv.x, L, st[6]);
                    st[7] = fmaf(tv.y, L, st[7]);
                    st[8] = fmaf(tv.x, L2, st[8]);
                    if ((p0 != 0) && (gi != (jbase + col))) {
                        st[0] += 1.0f;
                        st[1] += L;
                        st[2] += L2;
                    }
                }
            }
            #pragma unroll
            for (int s = 0; s < 9; s++) {
                float v = st[s];
                v += __shfl_xor_sync(0xffffffffu, v, 1);
                v += __shfl_xor_sync(0xffffffffu, v, 2);
                st[s] = v;
            }
            if ((lane & 3) == 0) {
                #pragma unroll
                for (int s = 0; s < 9; s++) {
                    sred[(row * 4 + wc) * 9 + s] = st[s];
                }
            }
        }
    }
    __syncthreads();

    if (tid < 128) {
        #pragma unroll
        for (int s = 0; s < 9; s++) {
            float v = sred[(tid * 4 + 0) * 9 + s] + sred[(tid * 4 + 1) * 9 + s] +
                      sred[(tid * 4 + 2) * 9 + s] + sred[(tid * 4 + 3) * 9 + s];
            g_part[((ibase + tid) * 9 + s) * NBJ + blockIdx.x] = v;
        }
    }
}

__global__ void combine1_kernel() {
    __shared__ float sh[256];
    int i = blockIdx.x * 256 + threadIdx.x;
    float agg[9];
    #pragma unroll
    for (int s = 0; s < 9; s++) {
        const float4* p = (const float4*)&g_part[(i * 9 + s) * NBJ];
        float sum = 0.0f;
        #pragma unroll
        for (int q = 0; q < NBJ / 4; q++) {
            float4 tv = p[q];
            sum += tv.x + tv.y + tv.z + tv.w;
        }
        agg[s] = sum;
    }
    float rl = agg[2] * agg[3] - 2.0f * agg[1] * (agg[6] + agg[4])
             + agg[0] * (agg[8] + 2.0f * agg[7] + agg[5]);
    sh[threadIdx.x] = rl;
    __syncthreads();
    for (int o = 128; o > 0; o >>= 1) {
        if (threadIdx.x < o) sh[threadIdx.x] += sh[threadIdx.x + o];
        __syncthreads();
    }
    if (threadIdx.x == 0) g_bsum[blockIdx.x] = sh[0];
}

__global__ void combine2_kernel(float* __restrict__ out) {
    if (threadIdx.x == 0) {
        float s = 0.0f;
        #pragma unroll
        for (int b = 0; b < 16; b++) s += g_bsum[b];
        out[0] = s;
    }
}

extern "C" void kernel_launch(void* const* d_in, const int* in_sizes, int n_in,
                              void* d_out, int out_size) {
    (void)in_sizes; (void)n_in; (void)out_size;
    const float* X = (const float*)d_in[0];
    const int* labels = (const int*)d_in[1];
    float* out = (float*)d_out;

    const double lg = log(0.1 + 1e-6);
    float a[4];
    for (int m = 0; m < 4; m++) {
        a[m] = (float)(0.1 * (lg - log(pow(0.1, (double)(5 - m)) + 1e-6)));
    }

    cudaFuncSetAttribute(tile_kernel, cudaFuncAttributeMaxDynamicSharedMemorySize, SMEM_BYTES);

    detect_kernel<<<1, 256>>>(labels);
    dim3 grid(NBJ, NBJ);
    tile_kernel<<<grid, 256, SMEM_BYTES>>>(X, labels, a[0], a[1], a[2], a[3]);
    combine1_kernel<<<16, 256>>>();
    combine2_kernel<<<1, 32>>>(out);
}

// round 8
// speedup vs baseline: 4.1622x; 1.2300x over previous
#include <cuda_runtime.h>
#include <cuda_bf16.h>
#include <cstdint>
#include <math.h>

typedef unsigned int u32;

#define N 4096
#define KK 4
#define TS 128
#define NBJ (N / TS)
#define NPAIR 496
#define NBLK 528
#define EPSF 1e-6f

__device__ float g_part[N * 9 * NBJ];
__device__ float g_bsum[16];
__device__ u32   g_arrive = 0;

__device__ __forceinline__ u32 smem_u32(const void* p) {
    u32 a;
    asm("{ .reg .u64 t; cvta.to.shared.u64 t, %1; cvt.u32.u64 %0, t; }" : "=r"(a) : "l"(p));
    return a;
}

__device__ __forceinline__ void ldsm_x4(u32* r, u32 addr) {
    asm volatile("ldmatrix.sync.aligned.m8n8.x4.shared.b16 {%0,%1,%2,%3}, [%4];"
                 : "=r"(r[0]), "=r"(r[1]), "=r"(r[2]), "=r"(r[3]) : "r"(addr));
}

__device__ __forceinline__ void ldsm_x2(u32* r, u32 addr) {
    asm volatile("ldmatrix.sync.aligned.m8n8.x2.shared.b16 {%0,%1}, [%2];"
                 : "=r"(r[0]), "=r"(r[1]) : "r"(addr));
}

__device__ __forceinline__ void mma_bf16(float* c, const u32* a, const u32* b) {
    asm volatile(
        "mma.sync.aligned.m16n8k16.row.col.f32.bf16.bf16.f32 "
        "{%0,%1,%2,%3}, {%4,%5,%6,%7}, {%8,%9}, {%0,%1,%2,%3};"
        : "+f"(c[0]), "+f"(c[1]), "+f"(c[2]), "+f"(c[3])
        : "r"(a[0]), "r"(a[1]), "r"(a[2]), "r"(a[3]), "r"(b[0]), "r"(b[1]));
}

#define OFF_AHI   0
#define OFF_ALO   32768
#define OFF_BHI   65536
#define OFF_BLO   98304
#define OFF_TBL   131072
#define OFF_STI   131328
#define OFF_STJ   131840
#define OFF_LABI  132352
#define OFF_LABJ  134400
#define SMEM_BYTES 136448

// sred1 (rows x 4 wc x 9) at offset 0 (18KB), sred2 (cols x 2 wr x 9) at 32768 (9KB)
#define OFF_SRED1 0
#define OFF_SRED2 32768

// Tile row layout: 128 rows x 256 bytes (128 bf16), 16B blocks XOR-swizzled.
__device__ __forceinline__ int sw_addr(int row, int c16) {
    return row * 256 + ((c16 ^ (row & 7)) << 4);
}

__global__ __launch_bounds__(256) void tile_kernel(
    const float* __restrict__ X,
    const int* __restrict__ labels,
    float a0, float a1, float a2, float a3)
{
    extern __shared__ char smem[];
    const u32 sbase = smem_u32(smem);
    float4* tbl = (float4*)(smem + OFF_TBL);
    int* sTi = (int*)(smem + OFF_STI);
    int* sTj = (int*)(smem + OFF_STJ);
    int4* sLabI = (int4*)(smem + OFF_LABI);
    int4* sLabJ = (int4*)(smem + OFF_LABJ);
    __shared__ int sES;

    const int tid = threadIdx.x;
    const int lane = tid & 31;
    const int wid = tid >> 5;
    const int wr = wid >> 2;
    const int wc = wid & 3;

    // decode block -> (bi, bj), off-diagonal pairs first, diagonals last
    int bi;
    int bj;
    if (blockIdx.x < NPAIR) {
        int rem = blockIdx.x;
        bi = 0;
        while (rem >= 31 - bi) {
            rem -= 31 - bi;
            bi++;
        }
        bj = bi + 1 + rem;
    } else {
        bi = blockIdx.x - NPAIR;
        bj = bi;
    }
    const int isdiag = (bi == bj) ? 1 : 0;
    const int ibase = bi * TS;
    const int jbase = bj * TS;

    // ---- in-tile labels layout detection (int64 vs int32) ----
    if (wid == 0) {
        int v = 0;
        if (lane < 16) v = labels[2 * lane + 1];
        u32 m = __ballot_sync(0xffffffffu, v != 0);
        if (lane == 0) sES = (m != 0) ? 1 : 2;
    }
    __syncthreads();
    const int es = sES;

    // ---- load X tiles, split fp32 -> bf16 hi/lo, store swizzled ----
    const float4* Xg = (const float4*)X;   // X: [4096][32] float4
    #pragma unroll
    for (int it = 0; it < 16; it++) {
        int idx = tid + it * 256;
        int row = idx >> 5;
        int c8 = idx & 31;
        int off = sw_addr(row, c8 >> 1) + (c8 & 1) * 8;
        float4 va = Xg[(ibase + row) * 32 + c8];
        float4 vb = Xg[(jbase + row) * 32 + c8];
        #pragma unroll
        for (int t2 = 0; t2 < 2; t2++) {
            float4 v = (t2 != 0) ? vb : va;
            unsigned hx = (unsigned)__bfloat16_as_ushort(__float2bfloat16(v.x));
            unsigned hy = (unsigned)__bfloat16_as_ushort(__float2bfloat16(v.y));
            unsigned hz = (unsigned)__bfloat16_as_ushort(__float2bfloat16(v.z));
            unsigned hw = (unsigned)__bfloat16_as_ushort(__float2bfloat16(v.w));
            float lx = v.x - __bfloat162float(__ushort_as_bfloat16((unsigned short)hx));
            float ly = v.y - __bfloat162float(__ushort_as_bfloat16((unsigned short)hy));
            float lz = v.z - __bfloat162float(__ushort_as_bfloat16((unsigned short)hz));
            float lw = v.w - __bfloat162float(__ushort_as_bfloat16((unsigned short)hw));
            uint2 hv;
            hv.x = hx | (hy << 16);
            hv.y = hz | (hw << 16);
            uint2 lv;
            lv.x = (unsigned)__bfloat16_as_ushort(__float2bfloat16(lx)) |
                   ((unsigned)__bfloat16_as_ushort(__float2bfloat16(ly)) << 16);
            lv.y = (unsigned)__bfloat16_as_ushort(__float2bfloat16(lz)) |
                   ((unsigned)__bfloat16_as_ushort(__float2bfloat16(lw)) << 16);
            int hofs = (t2 != 0) ? OFF_BHI : OFF_AHI;
            int lofs = (t2 != 0) ? OFF_BLO : OFF_ALO;
            *(uint2*)(smem + hofs + off) = hv;
            *(uint2*)(smem + lofs + off) = lv;
        }
    }

    // ---- labels for both blocks + neg-pattern table ----
    if (tid < 128) {
        int gi = ibase + tid;
        sTi[tid] = labels[(gi * KK) * es];
        int4 lv4;
        lv4.x = labels[(gi * KK + 0) * es];
        lv4.y = labels[(gi * KK + 1) * es];
        lv4.z = labels[(gi * KK + 2) * es];
        lv4.w = labels[(gi * KK + 3) * es];
        sLabI[tid] = lv4;
        if (tid < 16) {
            int eb = tid;
            int e0 = eb & 1;
            int e1 = (eb >> 1) & 1;
            int e2 = (eb >> 2) & 1;
            int e3 = (eb >> 3) & 1;
            int n0 = 1 - e3;
            int n1 = (1 - e2) & e3;
            int n2 = (1 - e1) & e2;
            int n3 = (1 - e0) & e1;
            float kcnt = (float)(n0 + n1 + n2 + n3);
            float sa = n0 * a0 + n1 * a1 + n2 * a2 + n3 * a3;
            float sa2 = n0 * a0 * a0 + n1 * a1 * a1 + n2 * a2 * a2 + n3 * a3 * a3;
            tbl[eb] = make_float4(kcnt, sa, sa2, 0.0f);
        }
    } else {
        int r = tid - 128;
        int gj = jbase + r;
        sTj[r] = labels[(gj * KK) * es];
        int4 lv4;
        lv4.x = labels[(gj * KK + 0) * es];
        lv4.y = labels[(gj * KK + 1) * es];
        lv4.z = labels[(gj * KK + 2) * es];
        lv4.w = labels[(gj * KK + 3) * es];
        sLabJ[r] = lv4;
    }
    __syncthreads();

    // ---- GEMM mainloop: hi*hi + hi*lo + lo*hi via mma.sync bf16 ----
    float acc[4][4][4];
    #pragma unroll
    for (int mt = 0; mt < 4; mt++)
        #pragma unroll
        for (int nt = 0; nt < 4; nt++)
            #pragma unroll
            for (int q = 0; q < 4; q++)
                acc[mt][nt][q] = 0.0f;

    const int a_row = lane & 15;
    const int a_k = lane >> 4;
    const int b_row = lane & 7;
    const int b_k = (lane >> 3) & 1;

    #pragma unroll
    for (int ks = 0; ks < 8; ks++) {
        u32 bh[4][2];
        u32 bl[4][2];
        int c16b = ks * 2 + b_k;
        #pragma unroll
        for (int nt = 0; nt < 4; nt++) {
            int r = wc * 32 + nt * 8 + b_row;
            u32 ad = (u32)sw_addr(r, c16b);
            ldsm_x2(bh[nt], sbase + OFF_BHI + ad);
            ldsm_x2(bl[nt], sbase + OFF_BLO + ad);
        }
        int c16a = ks * 2 + a_k;
        #pragma unroll
        for (int mt = 0; mt < 4; mt++) {
            int r = wr * 64 + mt * 16 + a_row;
            u32 ad = (u32)sw_addr(r, c16a);
            u32 ah[4];
            u32 al[4];
            ldsm_x4(ah, sbase + OFF_AHI + ad);
            ldsm_x4(al, sbase + OFF_ALO + ad);
            #pragma unroll
            for (int nt = 0; nt < 4; nt++) {
                mma_bf16(acc[mt][nt], ah, bh[nt]);
                mma_bf16(acc[mt][nt], ah, bl[nt]);
                mma_bf16(acc[mt][nt], al, bh[nt]);
            }
        }
    }

    __syncthreads();   // tile smem regions now free for reduce scratch

    // ---- convert acc -> log in place (each log serves both orientations) ----
    #pragma unroll
    for (int mt = 0; mt < 4; mt++)
        #pragma unroll
        for (int nt = 0; nt < 4; nt++)
            #pragma unroll
            for (int q = 0; q < 4; q++)
                acc[mt][nt][q] = __logf(acc[mt][nt][q] + EPSF);

    float* sred1 = (float*)(smem + OFF_SRED1);
    float* sred2 = (float*)(smem + OFF_SRED2);

    // ---- orientation 1: stats for i-block rows over j-block cols ----
    #pragma unroll
    for (int mt = 0; mt < 4; mt++) {
        #pragma unroll
        for (int h = 0; h < 2; h++) {
            int row = wr * 64 + mt * 16 + (lane >> 2) + h * 8;
            int tlab = sTi[row];
            int selfcol = (isdiag != 0) ? row : -1;
            float st[9];
            #pragma unroll
            for (int s = 0; s < 9; s++) st[s] = 0.0f;
            #pragma unroll
            for (int nt = 0; nt < 4; nt++) {
                #pragma unroll
                for (int e = 0; e < 2; e++) {
                    float L = acc[mt][nt][h * 2 + e];
                    float L2 = L * L;
                    int col = wc * 32 + nt * 8 + ((lane & 3) << 1) + e;
                    int4 lbv = sLabJ[col];
                    int p0 = (tlab == lbv.x) ? 1 : 0;
                    int eb = p0 | (((tlab == lbv.y) ? 1 : 0) << 1) |
                             (((tlab == lbv.z) ? 1 : 0) << 2) |
                             (((tlab == lbv.w) ? 1 : 0) << 3);
                    float4 tv = tbl[eb];
                    st[3] += tv.x;
                    st[4] += tv.y;
                    st[5] += tv.z;
                    st[6] = fmaf(tv.x, L, st[6]);
                    st[7] = fmaf(tv.y, L, st[7]);
                    st[8] = fmaf(tv.x, L2, st[8]);
                    if ((p0 != 0) && (col != selfcol)) {
                        st[0] += 1.0f;
                        st[1] += L;
                        st[2] += L2;
                    }
                }
            }
            #pragma unroll
            for (int s = 0; s < 9; s++) {
                float v = st[s];
                v += __shfl_xor_sync(0xffffffffu, v, 1);
                v += __shfl_xor_sync(0xffffffffu, v, 2);
                st[s] = v;
            }
            if ((lane & 3) == 0) {
                #pragma unroll
                for (int s = 0; s < 9; s++) sred1[(row * 4 + wc) * 9 + s] = st[s];
            }
        }
    }

    // ---- orientation 2 (off-diag only): stats for j-block rows over i-block cols ----
    if (isdiag == 0) {
        #pragma unroll
        for (int nt = 0; nt < 4; nt++) {
            #pragma unroll
            for (int e = 0; e < 2; e++) {
                int col = wc * 32 + nt * 8 + ((lane & 3) << 1) + e;
                int tlab2 = sTj[col];
                float st[9];
                #pragma unroll
                for (int s = 0; s < 9; s++) st[s] = 0.0f;
                #pragma unroll
                for (int mt = 0; mt < 4; mt++) {
                    #pragma unroll
                    for (int h = 0; h < 2; h++) {
                        float L = acc[mt][nt][h * 2 + e];
                        float L2 = L * L;
                        int row = wr * 64 + mt * 16 + (lane >> 2) + h * 8;
                        int4 lbv = sLabI[row];
                        int p0 = (tlab2 == lbv.x) ? 1 : 0;
                        int eb = p0 | (((tlab2 == lbv.y) ? 1 : 0) << 1) |
                                 (((tlab2 == lbv.z) ? 1 : 0) << 2) |
                                 (((tlab2 == lbv.w) ? 1 : 0) << 3);
                        float4 tv = tbl[eb];
                        st[3] += tv.x;
                        st[4] += tv.y;
                        st[5] += tv.z;
                        st[6] = fmaf(tv.x, L, st[6]);
                        st[7] = fmaf(tv.y, L, st[7]);
                        st[8] = fmaf(tv.x, L2, st[8]);
                        if (p0 != 0) {
                            st[0] += 1.0f;
                            st[1] += L;
                            st[2] += L2;
                        }
                    }
                }
                #pragma unroll
                for (int s = 0; s < 9; s++) {
                    float v = st[s];
                    v += __shfl_xor_sync(0xffffffffu, v, 4);
                    v += __shfl_xor_sync(0xffffffffu, v, 8);
                    v += __shfl_xor_sync(0xffffffffu, v, 16);
                    st[s] = v;
                }
                if ((lane >> 2) == 0) {
                    #pragma unroll
                    for (int s = 0; s < 9; s++) sred2[(col * 2 + wr) * 9 + s] = st[s];
                }
            }
        }
    }
    __syncthreads();

    // ---- final combines, write-once g_part ----
    if (tid < 128) {
        #pragma unroll
        for (int s = 0; s < 9; s++) {
            float v = sred1[(tid * 4 + 0) * 9 + s] + sred1[(tid * 4 + 1) * 9 + s] +
                      sred1[(tid * 4 + 2) * 9 + s] + sred1[(tid * 4 + 3) * 9 + s];
            g_part[((ibase + tid) * 9 + s) * NBJ + bj] = v;
        }
    } else if (isdiag == 0) {
        int c2 = tid - 128;
        #pragma unroll
        for (int s = 0; s < 9; s++) {
            float v = sred2[(c2 * 2 + 0) * 9 + s] + sred2[(c2 * 2 + 1) * 9 + s];
            g_part[((jbase + c2) * 9 + s) * NBJ + bi] = v;
        }
    }
}

__global__ void combine_kernel(float* __restrict__ out) {
    __shared__ float sh[256];
    __shared__ u32 ticket;
    int i = blockIdx.x * 256 + threadIdx.x;
    float agg[9];
    #pragma unroll
    for (int s = 0; s < 9; s++) {
        const float4* p = (const float4*)&g_part[(i * 9 + s) * NBJ];
        float sum = 0.0f;
        #pragma unroll
        for (int q = 0; q < NBJ / 4; q++) {
            float4 tv = p[q];
            sum += tv.x + tv.y + tv.z + tv.w;
        }
        agg[s] = sum;
    }
    float rl = agg[2] * agg[3] - 2.0f * agg[1] * (agg[6] + agg[4])
             + agg[0] * (agg[8] + 2.0f * agg[7] + agg[5]);
    sh[threadIdx.x] = rl;
    __syncthreads();
    for (int o = 128; o > 0; o >>= 1) {
        if (threadIdx.x < o) sh[threadIdx.x] += sh[threadIdx.x + o];
        __syncthreads();
    }
    if (threadIdx.x == 0) {
        g_bsum[blockIdx.x] = sh[0];
        __threadfence();
        ticket = atomicAdd(&g_arrive, 1u);
    }
    __syncthreads();
    if (threadIdx.x == 0 && ticket == 15u) {
        __threadfence();
        float s = 0.0f;
        #pragma unroll
        for (int b = 0; b < 16; b++) s += g_bsum[b];
        out[0] = s;
        g_arrive = 0;   // reset for next (graph-replayed) launch
    }
}

extern "C" void kernel_launch(void* const* d_in, const int* in_sizes, int n_in,
                              void* d_out, int out_size) {
    (void)in_sizes; (void)n_in; (void)out_size;
    const float* X = (const float*)d_in[0];
    const int* labels = (const int*)d_in[1];
    float* out = (float*)d_out;

    const double lg = log(0.1 + 1e-6);
    float a[4];
    for (int m = 0; m < 4; m++) {
        a[m] = (float)(0.1 * (lg - log(pow(0.1, (double)(5 - m)) + 1e-6)));
    }

    cudaFuncSetAttribute(tile_kernel, cudaFuncAttributeMaxDynamicSharedMemorySize, SMEM_BYTES);

    tile_kernel<<<NBLK, 256, SMEM_BYTES>>>(X, labels, a[0], a[1], a[2], a[3]);
    combine_kernel<<<16, 256>>>(out);
}

// round 9
// speedup vs baseline: 4.5024x; 1.0817x over previous
#include <cuda_runtime.h>
#include <cuda_bf16.h>
#include <cstdint>
#include <math.h>

typedef unsigned int u32;

#define N 4096
#define KK 4
#define TS 128
#define NBJ (N / TS)
#define NPAIR 496
#define NBLK 528
#define EPSF 1e-6f
#define CBLK 64

__device__ float g_part[N * 9 * NBJ];
__device__ float g_bsum[CBLK];
__device__ u32   g_arrive = 0;

__device__ __forceinline__ u32 smem_u32(const void* p) {
    u32 a;
    asm("{ .reg .u64 t; cvta.to.shared.u64 t, %1; cvt.u32.u64 %0, t; }" : "=r"(a) : "l"(p));
    return a;
}

__device__ __forceinline__ void ldsm_x4(u32* r, u32 addr) {
    asm volatile("ldmatrix.sync.aligned.m8n8.x4.shared.b16 {%0,%1,%2,%3}, [%4];"
                 : "=r"(r[0]), "=r"(r[1]), "=r"(r[2]), "=r"(r[3]) : "r"(addr));
}

__device__ __forceinline__ void ldsm_x2(u32* r, u32 addr) {
    asm volatile("ldmatrix.sync.aligned.m8n8.x2.shared.b16 {%0,%1}, [%2];"
                 : "=r"(r[0]), "=r"(r[1]) : "r"(addr));
}

__device__ __forceinline__ void mma_bf16(float* c, const u32* a, const u32* b) {
    asm volatile(
        "mma.sync.aligned.m16n8k16.row.col.f32.bf16.bf16.f32 "
        "{%0,%1,%2,%3}, {%4,%5,%6,%7}, {%8,%9}, {%0,%1,%2,%3};"
        : "+f"(c[0]), "+f"(c[1]), "+f"(c[2]), "+f"(c[3])
        : "r"(a[0]), "r"(a[1]), "r"(a[2]), "r"(a[3]), "r"(b[0]), "r"(b[1]));
}

#define OFF_AHI   0
#define OFF_ALO   32768
#define OFF_BHI   65536
#define OFF_BLO   98304
#define OFF_TBL   131072
#define OFF_STI   131328
#define OFF_STJ   131840
#define OFF_LABI  132352
#define OFF_LABJ  134400
#define SMEM_BYTES 136448

#define OFF_SRED1 0
#define OFF_SRED2 32768

// Tile row layout: 128 rows x 256 bytes (128 bf16), 16B blocks XOR-swizzled.
__device__ __forceinline__ int sw_addr(int row, int c16) {
    return row * 256 + ((c16 ^ (row & 7)) << 4);
}

__global__ __launch_bounds__(256) void tile_kernel(
    const float* __restrict__ X,
    const int* __restrict__ labels,
    float a0, float a1, float a2, float a3)
{
    extern __shared__ char smem[];
    const u32 sbase = smem_u32(smem);
    float4* tbl = (float4*)(smem + OFF_TBL);
    int* sTi = (int*)(smem + OFF_STI);
    int* sTj = (int*)(smem + OFF_STJ);
    int4* sLabI = (int4*)(smem + OFF_LABI);
    int4* sLabJ = (int4*)(smem + OFF_LABJ);
    __shared__ int sES;

    const int tid = threadIdx.x;
    const int lane = tid & 31;
    const int wid = tid >> 5;
    const int wr = wid >> 2;
    const int wc = wid & 3;

    // decode block -> (bi, bj), off-diagonal pairs first, diagonals last
    int bi;
    int bj;
    if (blockIdx.x < NPAIR) {
        int rem = blockIdx.x;
        bi = 0;
        while (rem >= 31 - bi) {
            rem -= 31 - bi;
            bi++;
        }
        bj = bi + 1 + rem;
    } else {
        bi = blockIdx.x - NPAIR;
        bj = bi;
    }
    const int isdiag = (bi == bj) ? 1 : 0;
    const int ibase = bi * TS;
    const int jbase = bj * TS;

    // ---- in-tile labels layout detection (int64 vs int32) ----
    if (wid == 0) {
        int v = 0;
        if (lane < 16) v = labels[2 * lane + 1];
        u32 m = __ballot_sync(0xffffffffu, v != 0);
        if (lane == 0) sES = (m != 0) ? 1 : 2;
    }
    __syncthreads();
    const int es = sES;

    // ---- load X tiles, split fp32 -> bf16 hi/lo, store swizzled ----
    const float4* Xg = (const float4*)X;   // X: [4096][32] float4
    #pragma unroll
    for (int it = 0; it < 16; it++) {
        int idx = tid + it * 256;
        int row = idx >> 5;
        int c8 = idx & 31;
        int off = sw_addr(row, c8 >> 1) + (c8 & 1) * 8;
        float4 va = Xg[(ibase + row) * 32 + c8];
        float4 vb = Xg[(jbase + row) * 32 + c8];
        #pragma unroll
        for (int t2 = 0; t2 < 2; t2++) {
            float4 v = (t2 != 0) ? vb : va;
            unsigned hx = (unsigned)__bfloat16_as_ushort(__float2bfloat16(v.x));
            unsigned hy = (unsigned)__bfloat16_as_ushort(__float2bfloat16(v.y));
            unsigned hz = (unsigned)__bfloat16_as_ushort(__float2bfloat16(v.z));
            unsigned hw = (unsigned)__bfloat16_as_ushort(__float2bfloat16(v.w));
            float lx = v.x - __bfloat162float(__ushort_as_bfloat16((unsigned short)hx));
            float ly = v.y - __bfloat162float(__ushort_as_bfloat16((unsigned short)hy));
            float lz = v.z - __bfloat162float(__ushort_as_bfloat16((unsigned short)hz));
            float lw = v.w - __bfloat162float(__ushort_as_bfloat16((unsigned short)hw));
            uint2 hv;
            hv.x = hx | (hy << 16);
            hv.y = hz | (hw << 16);
            uint2 lv;
            lv.x = (unsigned)__bfloat16_as_ushort(__float2bfloat16(lx)) |
                   ((unsigned)__bfloat16_as_ushort(__float2bfloat16(ly)) << 16);
            lv.y = (unsigned)__bfloat16_as_ushort(__float2bfloat16(lz)) |
                   ((unsigned)__bfloat16_as_ushort(__float2bfloat16(lw)) << 16);
            int hofs = (t2 != 0) ? OFF_BHI : OFF_AHI;
            int lofs = (t2 != 0) ? OFF_BLO : OFF_ALO;
            *(uint2*)(smem + hofs + off) = hv;
            *(uint2*)(smem + lofs + off) = lv;
        }
    }

    // ---- labels for both blocks + neg-pattern table ----
    if (tid < 128) {
        int gi = ibase + tid;
        sTi[tid] = labels[(gi * KK) * es];
        int4 lv4;
        lv4.x = labels[(gi * KK + 0) * es];
        lv4.y = labels[(gi * KK + 1) * es];
        lv4.z = labels[(gi * KK + 2) * es];
        lv4.w = labels[(gi * KK + 3) * es];
        sLabI[tid] = lv4;
        if (tid < 16) {
            int eb = tid;
            int e0 = eb & 1;
            int e1 = (eb >> 1) & 1;
            int e2 = (eb >> 2) & 1;
            int e3 = (eb >> 3) & 1;
            int n0 = 1 - e3;
            int n1 = (1 - e2) & e3;
            int n2 = (1 - e1) & e2;
            int n3 = (1 - e0) & e1;
            float kcnt = (float)(n0 + n1 + n2 + n3);
            float sa = n0 * a0 + n1 * a1 + n2 * a2 + n3 * a3;
            float sa2 = n0 * a0 * a0 + n1 * a1 * a1 + n2 * a2 * a2 + n3 * a3 * a3;
            tbl[eb] = make_float4(kcnt, sa, sa2, 0.0f);
        }
    } else {
        int r = tid - 128;
        int gj = jbase + r;
        sTj[r] = labels[(gj * KK) * es];
        int4 lv4;
        lv4.x = labels[(gj * KK + 0) * es];
        lv4.y = labels[(gj * KK + 1) * es];
        lv4.z = labels[(gj * KK + 2) * es];
        lv4.w = labels[(gj * KK + 3) * es];
        sLabJ[r] = lv4;
    }
    __syncthreads();

    // ---- GEMM mainloop: hi*hi + hi*lo + lo*hi via mma.sync bf16 ----
    float acc[4][4][4];
    #pragma unroll
    for (int mt = 0; mt < 4; mt++)
        #pragma unroll
        for (int nt = 0; nt < 4; nt++)
            #pragma unroll
            for (int q = 0; q < 4; q++)
                acc[mt][nt][q] = 0.0f;

    const int a_row = lane & 15;
    const int a_k = lane >> 4;
    const int b_row = lane & 7;
    const int b_k = (lane >> 3) & 1;

    #pragma unroll
    for (int ks = 0; ks < 8; ks++) {
        u32 bh[4][2];
        u32 bl[4][2];
        int c16b = ks * 2 + b_k;
        #pragma unroll
        for (int nt = 0; nt < 4; nt++) {
            int r = wc * 32 + nt * 8 + b_row;
            u32 ad = (u32)sw_addr(r, c16b);
            ldsm_x2(bh[nt], sbase + OFF_BHI + ad);
            ldsm_x2(bl[nt], sbase + OFF_BLO + ad);
        }
        int c16a = ks * 2 + a_k;
        #pragma unroll
        for (int mt = 0; mt < 4; mt++) {
            int r = wr * 64 + mt * 16 + a_row;
            u32 ad = (u32)sw_addr(r, c16a);
            u32 ah[4];
            u32 al[4];
            ldsm_x4(ah, sbase + OFF_AHI + ad);
            ldsm_x4(al, sbase + OFF_ALO + ad);
            #pragma unroll
            for (int nt = 0; nt < 4; nt++) {
                mma_bf16(acc[mt][nt], ah, bh[nt]);
                mma_bf16(acc[mt][nt], ah, bl[nt]);
                mma_bf16(acc[mt][nt], al, bh[nt]);
            }
        }
    }

    __syncthreads();   // tile smem regions now free for reduce scratch

    // ---- convert acc -> log in place (each log serves both orientations) ----
    #pragma unroll
    for (int mt = 0; mt < 4; mt++)
        #pragma unroll
        for (int nt = 0; nt < 4; nt++)
            #pragma unroll
            for (int q = 0; q < 4; q++)
                acc[mt][nt][q] = __logf(acc[mt][nt][q] + EPSF);

    float* sred1 = (float*)(smem + OFF_SRED1);
    float* sred2 = (float*)(smem + OFF_SRED2);

    // ---- orientation 1: stats for i-block rows over j-block cols ----
    #pragma unroll
    for (int mt = 0; mt < 4; mt++) {
        #pragma unroll
        for (int h = 0; h < 2; h++) {
            int row = wr * 64 + mt * 16 + (lane >> 2) + h * 8;
            int tlab = sTi[row];
            int selfcol = (isdiag != 0) ? row : -1;
            float st[9];
            #pragma unroll
            for (int s = 0; s < 9; s++) st[s] = 0.0f;
            #pragma unroll
            for (int nt = 0; nt < 4; nt++) {
                #pragma unroll
                for (int e = 0; e < 2; e++) {
                    float L = acc[mt][nt][h * 2 + e];
                    float L2 = L * L;
                    int col = wc * 32 + nt * 8 + ((lane & 3) << 1) + e;
                    int4 lbv = sLabJ[col];
                    int p0 = (tlab == lbv.x) ? 1 : 0;
                    int eb = p0 | (((tlab == lbv.y) ? 1 : 0) << 1) |
                             (((tlab == lbv.z) ? 1 : 0) << 2) |
                             (((tlab == lbv.w) ? 1 : 0) << 3);
                    float4 tv = tbl[eb];
                    st[3] += tv.x;
                    st[4] += tv.y;
                    st[5] += tv.z;
                    st[6] = fmaf(tv.x, L, st[6]);
                    st[7] = fmaf(tv.y, L, st[7]);
                    st[8] = fmaf(tv.x, L2, st[8]);
                    if ((p0 != 0) && (col != selfcol)) {
                        st[0] += 1.0f;
                        st[1] += L;
                        st[2] += L2;
                    }
                }
            }
            #pragma unroll
            for (int s = 0; s < 9; s++) {
                float v = st[s];
                v += __shfl_xor_sync(0xffffffffu, v, 1);
                v += __shfl_xor_sync(0xffffffffu, v, 2);
                st[s] = v;
            }
            if ((lane & 3) == 0) {
                #pragma unroll
                for (int s = 0; s < 9; s++) sred1[(row * 4 + wc) * 9 + s] = st[s];
            }
        }
    }

    // ---- orientation 2 (off-diag only): stats for j-block rows over i-block cols ----
    if (isdiag == 0) {
        #pragma unroll
        for (int nt = 0; nt < 4; nt++) {
            #pragma unroll
            for (int e = 0; e < 2; e++) {
                int col = wc * 32 + nt * 8 + ((lane & 3) << 1) + e;
                int tlab2 = sTj[col];
                float st[9];
                #pragma unroll
                for (int s = 0; s < 9; s++) st[s] = 0.0f;
                #pragma unroll
                for (int mt = 0; mt < 4; mt++) {
                    #pragma unroll
                    for (int h = 0; h < 2; h++) {
                        float L = acc[mt][nt][h * 2 + e];
                        float L2 = L * L;
                        int row = wr * 64 + mt * 16 + (lane >> 2) + h * 8;
                        int4 lbv = sLabI[row];
                        int p0 = (tlab2 == lbv.x) ? 1 : 0;
                        int eb = p0 | (((tlab2 == lbv.y) ? 1 : 0) << 1) |
                                 (((tlab2 == lbv.z) ? 1 : 0) << 2) |
                                 (((tlab2 == lbv.w) ? 1 : 0) << 3);
                        float4 tv = tbl[eb];
                        st[3] += tv.x;
                        st[4] += tv.y;
                        st[5] += tv.z;
                        st[6] = fmaf(tv.x, L, st[6]);
                        st[7] = fmaf(tv.y, L, st[7]);
                        st[8] = fmaf(tv.x, L2, st[8]);
                        if (p0 != 0) {
                            st[0] += 1.0f;
                            st[1] += L;
                            st[2] += L2;
                        }
                    }
                }
                #pragma unroll
                for (int s = 0; s < 9; s++) {
                    float v = st[s];
                    v += __shfl_xor_sync(0xffffffffu, v, 4);
                    v += __shfl_xor_sync(0xffffffffu, v, 8);
                    v += __shfl_xor_sync(0xffffffffu, v, 16);
                    st[s] = v;
                }
                if ((lane >> 2) == 0) {
                    #pragma unroll
                    for (int s = 0; s < 9; s++) sred2[(col * 2 + wr) * 9 + s] = st[s];
                }
            }
        }
    }
    __syncthreads();

    // ---- final combines, write-once g_part ----
    if (tid < 128) {
        #pragma unroll
        for (int s = 0; s < 9; s++) {
            float v = sred1[(tid * 4 + 0) * 9 + s] + sred1[(tid * 4 + 1) * 9 + s] +
                      sred1[(tid * 4 + 2) * 9 + s] + sred1[(tid * 4 + 3) * 9 + s];
            g_part[((ibase + tid) * 9 + s) * NBJ + bj] = v;
        }
    } else if (isdiag == 0) {
        int c2 = tid - 128;
        #pragma unroll
        for (int s = 0; s < 9; s++) {
            float v = sred2[(c2 * 2 + 0) * 9 + s] + sred2[(c2 * 2 + 1) * 9 + s];
            g_part[((jbase + c2) * 9 + s) * NBJ + bi] = v;
        }
    }
}

// Combine: 64 blocks x 256 threads, 4 threads per row (8 col-blocks each),
// quad butterfly, per-block tree over 64 rows, ticket finalize (fixed order).
__global__ __launch_bounds__(256) void combine_kernel(float* __restrict__ out) {
    __shared__ float sh[CBLK];
    __shared__ u32 ticket;
    const int rowl = threadIdx.x >> 2;
    const int q = threadIdx.x & 3;
    const int row = blockIdx.x * 64 + rowl;

    float agg[9];
    #pragma unroll
    for (int s = 0; s < 9; s++) {
        const float4* p = (const float4*)&g_part[(row * 9 + s) * NBJ + q * 8];
        float4 t0 = p[0];
        float4 t1 = p[1];
        float v = (t0.x + t0.y) + (t0.z + t0.w) + (t1.x + t1.y) + (t1.z + t1.w);
        v += __shfl_xor_sync(0xffffffffu, v, 1);
        v += __shfl_xor_sync(0xffffffffu, v, 2);
        agg[s] = v;
    }
    float rl = agg[2] * agg[3] - 2.0f * agg[1] * (agg[6] + agg[4])
             + agg[0] * (agg[8] + 2.0f * agg[7] + agg[5]);
    if (q == 0) sh[rowl] = rl;
    __syncthreads();
    for (int o = 32; o > 0; o >>= 1) {
        if (threadIdx.x < (u32)o) sh[threadIdx.x] += sh[threadIdx.x + o];
        __syncthreads();
    }
    if (threadIdx.x == 0) {
        g_bsum[blockIdx.x] = sh[0];
        __threadfence();
        ticket = atomicAdd(&g_arrive, 1u);
    }
    __syncthreads();
    if (threadIdx.x == 0 && ticket == (CBLK - 1)) {
        __threadfence();
        float s = 0.0f;
        #pragma unroll
        for (int b = 0; b < CBLK; b++) s += g_bsum[b];
        out[0] = s;
        g_arrive = 0;   // reset for next (graph-replayed) launch
    }
}

extern "C" void kernel_launch(void* const* d_in, const int* in_sizes, int n_in,
                              void* d_out, int out_size) {
    (void)in_sizes; (void)n_in; (void)out_size;
    const float* X = (const float*)d_in[0];
    const int* labels = (const int*)d_in[1];
    float* out = (float*)d_out;

    const double lg = log(0.1 + 1e-6);
    float a[4];
    for (int m = 0; m < 4; m++) {
        a[m] = (float)(0.1 * (lg - log(pow(0.1, (double)(5 - m)) + 1e-6)));
    }

    cudaFuncSetAttribute(tile_kernel, cudaFuncAttributeMaxDynamicSharedMemorySize, SMEM_BYTES);

    tile_kernel<<<NBLK, 256, SMEM_BYTES>>>(X, labels, a[0], a[1], a[2], a[3]);
    combine_kernel<<<CBLK, 256>>>(out);
}

// round 10
// speedup vs baseline: 5.2440x; 1.1647x over previous
#include <cuda_runtime.h>
#include <cuda_bf16.h>
#include <cstdint>
#include <math.h>

typedef unsigned int u32;

#define N 4096
#define KK 4
#define TS 128
#define NBJ (N / TS)
#define NPAIR 496
#define NBLK 528
#define EPSF 1e-6f
#define CBLK 64

// g_part layout: [stat s][colblock cb][row] -> g_part[(s*NBJ+cb)*N + row]
__device__ float g_part[9 * NBJ * N];
__device__ float g_bsum[CBLK];
__device__ u32   g_arrive = 0;

__device__ __forceinline__ u32 smem_u32(const void* p) {
    u32 a;
    asm("{ .reg .u64 t; cvta.to.shared.u64 t, %1; cvt.u32.u64 %0, t; }" : "=r"(a) : "l"(p));
    return a;
}

__device__ __forceinline__ void ldsm_x4(u32* r, u32 addr) {
    asm volatile("ldmatrix.sync.aligned.m8n8.x4.shared.b16 {%0,%1,%2,%3}, [%4];"
                 : "=r"(r[0]), "=r"(r[1]), "=r"(r[2]), "=r"(r[3]) : "r"(addr));
}

__device__ __forceinline__ void ldsm_x2(u32* r, u32 addr) {
    asm volatile("ldmatrix.sync.aligned.m8n8.x2.shared.b16 {%0,%1}, [%2];"
                 : "=r"(r[0]), "=r"(r[1]) : "r"(addr));
}

__device__ __forceinline__ void mma_bf16(float* c, const u32* a, const u32* b) {
    asm volatile(
        "mma.sync.aligned.m16n8k16.row.col.f32.bf16.bf16.f32 "
        "{%0,%1,%2,%3}, {%4,%5,%6,%7}, {%8,%9}, {%0,%1,%2,%3};"
        : "+f"(c[0]), "+f"(c[1]), "+f"(c[2]), "+f"(c[3])
        : "r"(a[0]), "r"(a[1]), "r"(a[2]), "r"(a[3]), "r"(b[0]), "r"(b[1]));
}

// K-chunked tiles: 128 rows x 64 bf16 (128 bytes per row) = 16KB each
#define OFF_AHI   0
#define OFF_ALO   16384
#define OFF_BHI   32768
#define OFF_BLO   49152
#define OFF_TBL   65536
#define OFF_STI   65792
#define OFF_STJ   66304
#define OFF_LABI  66816
#define OFF_LABJ  68864
#define SMEM_BYTES 70912

#define OFF_SRED1 0
#define OFF_SRED2 20480

// Chunk tile row layout: 128 rows x 128 bytes (64 bf16), 16B blocks XOR-swizzled.
__device__ __forceinline__ int sw_addr(int row, int c16) {
    return row * 128 + ((c16 ^ (row & 7)) << 4);
}

__global__ __launch_bounds__(256, 2) void tile_kernel(
    const float* __restrict__ X,
    const int* __restrict__ labels,
    float a0, float a1, float a2, float a3)
{
    extern __shared__ char smem[];
    const u32 sbase = smem_u32(smem);
    float4* tbl = (float4*)(smem + OFF_TBL);
    int* sTi = (int*)(smem + OFF_STI);
    int* sTj = (int*)(smem + OFF_STJ);
    int4* sLabI = (int4*)(smem + OFF_LABI);
    int4* sLabJ = (int4*)(smem + OFF_LABJ);
    __shared__ int sES;

    const int tid = threadIdx.x;
    const int lane = tid & 31;
    const int wid = tid >> 5;
    const int wr = wid >> 2;
    const int wc = wid & 3;

    // decode block -> (bi, bj), off-diagonal pairs first, diagonals last
    int bi;
    int bj;
    if (blockIdx.x < NPAIR) {
        int rem = blockIdx.x;
        bi = 0;
        while (rem >= 31 - bi) {
            rem -= 31 - bi;
            bi++;
        }
        bj = bi + 1 + rem;
    } else {
        bi = blockIdx.x - NPAIR;
        bj = bi;
    }
    const int isdiag = (bi == bj) ? 1 : 0;
    const int ibase = bi * TS;
    const int jbase = bj * TS;

    // ---- labels layout detection (int64 vs int32) ----
    if (wid == 0) {
        int v = 0;
        if (lane < 16) v = labels[2 * lane + 1];
        u32 m = __ballot_sync(0xffffffffu, v != 0);
        if (lane == 0) sES = (m != 0) ? 1 : 2;
    }
    __syncthreads();
    const int es = sES;

    // ---- labels for both blocks + neg-pattern table ----
    if (tid < 128) {
        int gi = ibase + tid;
        sTi[tid] = labels[(gi * KK) * es];
        int4 lv4;
        lv4.x = labels[(gi * KK + 0) * es];
        lv4.y = labels[(gi * KK + 1) * es];
        lv4.z = labels[(gi * KK + 2) * es];
        lv4.w = labels[(gi * KK + 3) * es];
        sLabI[tid] = lv4;
        if (tid < 16) {
            int eb = tid;
            int e0 = eb & 1;
            int e1 = (eb >> 1) & 1;
            int e2 = (eb >> 2) & 1;
            int e3 = (eb >> 3) & 1;
            int n0 = 1 - e3;
            int n1 = (1 - e2) & e3;
            int n2 = (1 - e1) & e2;
            int n3 = (1 - e0) & e1;
            float kcnt = (float)(n0 + n1 + n2 + n3);
            float sa = n0 * a0 + n1 * a1 + n2 * a2 + n3 * a3;
            float sa2 = n0 * a0 * a0 + n1 * a1 * a1 + n2 * a2 * a2 + n3 * a3 * a3;
            tbl[eb] = make_float4(kcnt, sa, sa2, 0.0f);
        }
    } else {
        int r = tid - 128;
        int gj = jbase + r;
        sTj[r] = labels[(gj * KK) * es];
        int4 lv4;
        lv4.x = labels[(gj * KK + 0) * es];
        lv4.y = labels[(gj * KK + 1) * es];
        lv4.z = labels[(gj * KK + 2) * es];
        lv4.w = labels[(gj * KK + 3) * es];
        sLabJ[r] = lv4;
    }

    float acc[4][4][4];
    #pragma unroll
    for (int mt = 0; mt < 4; mt++)
        #pragma unroll
        for (int nt = 0; nt < 4; nt++)
            #pragma unroll
            for (int q = 0; q < 4; q++)
                acc[mt][nt][q] = 0.0f;

    const int a_row = lane & 15;
    const int a_k = lane >> 4;
    const int b_row = lane & 7;
    const int b_k = (lane >> 3) & 1;
    const float4* Xg = (const float4*)X;   // X: [4096][32] float4

    // ---- two K-chunks of 64: load chunk, run 4 k-steps, repeat ----
    #pragma unroll
    for (int chunk = 0; chunk < 2; chunk++) {
        __syncthreads();   // previous chunk consumed (or labels phase done)

        #pragma unroll
        for (int it = 0; it < 8; it++) {
            int idx = tid + it * 256;       // 0..2047
            int row = idx >> 4;
            int c8 = idx & 15;              // float4 index within chunk
            int off = sw_addr(row, c8 >> 1) + (c8 & 1) * 8;
            float4 va = Xg[(ibase + row) * 32 + chunk * 16 + c8];
            float4 vb = Xg[(jbase + row) * 32 + chunk * 16 + c8];
            #pragma unroll
            for (int t2 = 0; t2 < 2; t2++) {
                float4 v = (t2 != 0) ? vb : va;
                unsigned hx = (unsigned)__bfloat16_as_ushort(__float2bfloat16(v.x));
                unsigned hy = (unsigned)__bfloat16_as_ushort(__float2bfloat16(v.y));
                unsigned hz = (unsigned)__bfloat16_as_ushort(__float2bfloat16(v.z));
                unsigned hw = (unsigned)__bfloat16_as_ushort(__float2bfloat16(v.w));
                float lx = v.x - __bfloat162float(__ushort_as_bfloat16((unsigned short)hx));
                float ly = v.y - __bfloat162float(__ushort_as_bfloat16((unsigned short)hy));
                float lz = v.z - __bfloat162float(__ushort_as_bfloat16((unsigned short)hz));
                float lw = v.w - __bfloat162float(__ushort_as_bfloat16((unsigned short)hw));
                uint2 hv;
                hv.x = hx | (hy << 16);
                hv.y = hz | (hw << 16);
                uint2 lv;
                lv.x = (unsigned)__bfloat16_as_ushort(__float2bfloat16(lx)) |
                       ((unsigned)__bfloat16_as_ushort(__float2bfloat16(ly)) << 16);
                lv.y = (unsigned)__bfloat16_as_ushort(__float2bfloat16(lz)) |
                       ((unsigned)__bfloat16_as_ushort(__float2bfloat16(lw)) << 16);
                int hofs = (t2 != 0) ? OFF_BHI : OFF_AHI;
                int lofs = (t2 != 0) ? OFF_BLO : OFF_ALO;
                *(uint2*)(smem + hofs + off) = hv;
                *(uint2*)(smem + lofs + off) = lv;
            }
        }
        __syncthreads();

        #pragma unroll
        for (int ks = 0; ks < 4; ks++) {
            u32 bh[4][2];
            u32 bl[4][2];
            int c16b = ks * 2 + b_k;
            #pragma unroll
            for (int nt = 0; nt < 4; nt++) {
                int r = wc * 32 + nt * 8 + b_row;
                u32 ad = (u32)sw_addr(r, c16b);
                ldsm_x2(bh[nt], sbase + OFF_BHI + ad);
                ldsm_x2(bl[nt], sbase + OFF_BLO + ad);
            }
            int c16a = ks * 2 + a_k;
            #pragma unroll
            for (int mt = 0; mt < 4; mt++) {
                int r = wr * 64 + mt * 16 + a_row;
                u32 ad = (u32)sw_addr(r, c16a);
                u32 ah[4];
                u32 al[4];
                ldsm_x4(ah, sbase + OFF_AHI + ad);
                ldsm_x4(al, sbase + OFF_ALO + ad);
                #pragma unroll
                for (int nt = 0; nt < 4; nt++) {
                    mma_bf16(acc[mt][nt], ah, bh[nt]);
                    mma_bf16(acc[mt][nt], ah, bl[nt]);
                    mma_bf16(acc[mt][nt], al, bh[nt]);
                }
            }
        }
    }

    __syncthreads();   // tile smem regions now free for reduce scratch

    // ---- convert acc -> log in place ----
    #pragma unroll
    for (int mt = 0; mt < 4; mt++)
        #pragma unroll
        for (int nt = 0; nt < 4; nt++)
            #pragma unroll
            for (int q = 0; q < 4; q++)
                acc[mt][nt][q] = __logf(acc[mt][nt][q] + EPSF);

    float* sred1 = (float*)(smem + OFF_SRED1);
    float* sred2 = (float*)(smem + OFF_SRED2);

    // ---- orientation 1: stats for i-block rows over j-block cols ----
    #pragma unroll
    for (int mt = 0; mt < 4; mt++) {
        #pragma unroll
        for (int h = 0; h < 2; h++) {
            int row = wr * 64 + mt * 16 + (lane >> 2) + h * 8;
            int tlab = sTi[row];
            int selfcol = (isdiag != 0) ? row : -1;
            float st[9];
            #pragma unroll
            for (int s = 0; s < 9; s++) st[s] = 0.0f;
            #pragma unroll
            for (int nt = 0; nt < 4; nt++) {
                #pragma unroll
                for (int e = 0; e < 2; e++) {
                    float L = acc[mt][nt][h * 2 + e];
                    float L2 = L * L;
                    int col = wc * 32 + nt * 8 + ((lane & 3) << 1) + e;
                    int4 lbv = sLabJ[col];
                    int p0 = (tlab == lbv.x) ? 1 : 0;
                    int eb = p0 | (((tlab == lbv.y) ? 1 : 0) << 1) |
                             (((tlab == lbv.z) ? 1 : 0) << 2) |
                             (((tlab == lbv.w) ? 1 : 0) << 3);
                    float4 tv = tbl[eb];
                    st[3] += tv.x;
                    st[4] += tv.y;
                    st[5] += tv.z;
                    st[6] = fmaf(tv.x, L, st[6]);
                    st[7] = fmaf(tv.y, L, st[7]);
                    st[8] = fmaf(tv.x, L2, st[8]);
                    if ((p0 != 0) && (col != selfcol)) {
                        st[0] += 1.0f;
                        st[1] += L;
                        st[2] += L2;
                    }
                }
            }
            #pragma unroll
            for (int s = 0; s < 9; s++) {
                float v = st[s];
                v += __shfl_xor_sync(0xffffffffu, v, 1);
                v += __shfl_xor_sync(0xffffffffu, v, 2);
                st[s] = v;
            }
            if ((lane & 3) == 0) {
                #pragma unroll
                for (int s = 0; s < 9; s++) sred1[(row * 4 + wc) * 9 + s] = st[s];
            }
        }
    }

    // ---- orientation 2 (off-diag only): stats for j-block rows over i-block cols ----
    if (isdiag == 0) {
        #pragma unroll
        for (int nt = 0; nt < 4; nt++) {
            #pragma unroll
            for (int e = 0; e < 2; e++) {
                int col = wc * 32 + nt * 8 + ((lane & 3) << 1) + e;
                int tlab2 = sTj[col];
                float st[9];
                #pragma unroll
                for (int s = 0; s < 9; s++) st[s] = 0.0f;
                #pragma unroll
                for (int mt = 0; mt < 4; mt++) {
                    #pragma unroll
                    for (int h = 0; h < 2; h++) {
                        float L = acc[mt][nt][h * 2 + e];
                        float L2 = L * L;
                        int row = wr * 64 + mt * 16 + (lane >> 2) + h * 8;
                        int4 lbv = sLabI[row];
                        int p0 = (tlab2 == lbv.x) ? 1 : 0;
                        int eb = p0 | (((tlab2 == lbv.y) ? 1 : 0) << 1) |
                                 (((tlab2 == lbv.z) ? 1 : 0) << 2) |
                                 (((tlab2 == lbv.w) ? 1 : 0) << 3);
                        float4 tv = tbl[eb];
                        st[3] += tv.x;
                        st[4] += tv.y;
                        st[5] += tv.z;
                        st[6] = fmaf(tv.x, L, st[6]);
                        st[7] = fmaf(tv.y, L, st[7]);
                        st[8] = fmaf(tv.x, L2, st[8]);
                        if (p0 != 0) {
                            st[0] += 1.0f;
                            st[1] += L;
                            st[2] += L2;
                        }
                    }
                }
                #pragma unroll
                for (int s = 0; s < 9; s++) {
                    float v = st[s];
                    v += __shfl_xor_sync(0xffffffffu, v, 4);
                    v += __shfl_xor_sync(0xffffffffu, v, 8);
                    v += __shfl_xor_sync(0xffffffffu, v, 16);
                    st[s] = v;
                }
                if ((lane >> 2) == 0) {
                    #pragma unroll
                    for (int s = 0; s < 9; s++) sred2[(col * 2 + wr) * 9 + s] = st[s];
                }
            }
        }
    }
    __syncthreads();

    // ---- final combines; coalesced write-once g_part [s][cb][row] ----
    if (tid < 128) {
        #pragma unroll
        for (int s = 0; s < 9; s++) {
            float v = sred1[(tid * 4 + 0) * 9 + s] + sred1[(tid * 4 + 1) * 9 + s] +
                      sred1[(tid * 4 + 2) * 9 + s] + sred1[(tid * 4 + 3) * 9 + s];
            g_part[(s * NBJ + bj) * N + ibase + tid] = v;
        }
    } else if (isdiag == 0) {
        int c2 = tid - 128;
        #pragma unroll
        for (int s = 0; s < 9; s++) {
            float v = sred2[(c2 * 2 + 0) * 9 + s] + sred2[(c2 * 2 + 1) * 9 + s];
            g_part[(s * NBJ + bi) * N + jbase + c2] = v;
        }
    }
}

// Combine: 64 blocks x 256 threads, 4 threads per row (8 col-blocks each),
// coalesced reads, quad butterfly, per-block tree, ticket finalize.
__global__ __launch_bounds__(256) void combine_kernel(float* __restrict__ out) {
    __shared__ float sh[CBLK];
    __shared__ u32 ticket;
    const int rowl = threadIdx.x >> 2;
    const int q = threadIdx.x & 3;
    const int row = blockIdx.x * 64 + rowl;

    float agg[9];
    #pragma unroll
    for (int s = 0; s < 9; s++) {
        float v = 0.0f;
        #pragma unroll
        for (int k = 0; k < 8; k++) {
            v += g_part[(s * NBJ + q * 8 + k) * N + row];
        }
        v += __shfl_xor_sync(0xffffffffu, v, 1);
        v += __shfl_xor_sync(0xffffffffu, v, 2);
        agg[s] = v;
    }
    float rl = agg[2] * agg[3] - 2.0f * agg[1] * (agg[6] + agg[4])
             + agg[0] * (agg[8] + 2.0f * agg[7] + agg[5]);
    if (q == 0) sh[rowl] = rl;
    __syncthreads();
    for (int o = 32; o > 0; o >>= 1) {
        if (threadIdx.x < (u32)o) sh[threadIdx.x] += sh[threadIdx.x + o];
        __syncthreads();
    }
    if (threadIdx.x == 0) {
        g_bsum[blockIdx.x] = sh[0];
        __threadfence();
        ticket = atomicAdd(&g_arrive, 1u);
    }
    __syncthreads();
    if (threadIdx.x == 0 && ticket == (CBLK - 1)) {
        __threadfence();
        float s = 0.0f;
        #pragma unroll
        for (int b = 0; b < CBLK; b++) s += g_bsum[b];
        out[0] = s;
        g_arrive = 0;   // reset for next (graph-replayed) launch
    }
}

extern "C" void kernel_launch(void* const* d_in, const int* in_sizes, int n_in,
                              void* d_out, int out_size) {
    (void)in_sizes; (void)n_in; (void)out_size;
    const float* X = (const float*)d_in[0];
    const int* labels = (const int*)d_in[1];
    float* out = (float*)d_out;

    const double lg = log(0.1 + 1e-6);
    float a[4];
    for (int m = 0; m < 4; m++) {
        a[m] = (float)(0.1 * (lg - log(pow(0.1, (double)(5 - m)) + 1e-6)));
    }

    cudaFuncSetAttribute(tile_kernel, cudaFuncAttributeMaxDynamicSharedMemorySize, SMEM_BYTES);

    tile_kernel<<<NBLK, 256, SMEM_BYTES>>>(X, labels, a[0], a[1], a[2], a[3]);
    combine_kernel<<<CBLK, 256>>>(out);
}

// round 11
// speedup vs baseline: 5.6107x; 1.0699x over previous
#include <cuda_runtime.h>
#include <cuda_bf16.h>
#include <cstdint>
#include <math.h>

typedef unsigned int u32;
typedef unsigned long long u64;

#define N 4096
#define KK 4
#define TS 128
#define NBJ (N / TS)
#define NPAIR 496
#define NBLK 528
#define EPSF 1e-6f
#define CBLK 64

// g_part layout: [stat s][colblock cb][row] -> g_part[(s*NBJ+cb)*N + row]
__device__ float g_part[9 * NBJ * N];
__device__ float g_bsum[CBLK];
__device__ u32   g_arrive = 0;
__device__ int   g_estride;

// Pre-split, pre-swizzled bf16 tiles: [chunk(2)][row(4096)][128 bytes]
__device__ __align__(256) unsigned char g_xhi[2 * 4096 * 128];
__device__ __align__(256) unsigned char g_xlo[2 * 4096 * 128];

__device__ __forceinline__ u32 smem_u32(const void* p) {
    u32 a;
    asm("{ .reg .u64 t; cvta.to.shared.u64 t, %1; cvt.u32.u64 %0, t; }" : "=r"(a) : "l"(p));
    return a;
}

__device__ __forceinline__ void cp_async16(u32 smem_dst, const void* gsrc) {
    asm volatile("cp.async.cg.shared.global [%0], [%1], 16;"
                 :: "r"(smem_dst), "l"(gsrc) : "memory");
}

__device__ __forceinline__ void cp_commit_wait0() {
    asm volatile("cp.async.commit_group;" ::: "memory");
    asm volatile("cp.async.wait_group 0;" ::: "memory");
}

__device__ __forceinline__ void ldsm_x4(u32* r, u32 addr) {
    asm volatile("ldmatrix.sync.aligned.m8n8.x4.shared.b16 {%0,%1,%2,%3}, [%4];"
                 : "=r"(r[0]), "=r"(r[1]), "=r"(r[2]), "=r"(r[3]) : "r"(addr));
}

__device__ __forceinline__ void ldsm_x2(u32* r, u32 addr) {
    asm volatile("ldmatrix.sync.aligned.m8n8.x2.shared.b16 {%0,%1}, [%2];"
                 : "=r"(r[0]), "=r"(r[1]) : "r"(addr));
}

__device__ __forceinline__ void mma_bf16(float* c, const u32* a, const u32* b) {
    asm volatile(
        "mma.sync.aligned.m16n8k16.row.col.f32.bf16.bf16.f32 "
        "{%0,%1,%2,%3}, {%4,%5,%6,%7}, {%8,%9}, {%0,%1,%2,%3};"
        : "+f"(c[0]), "+f"(c[1]), "+f"(c[2]), "+f"(c[3])
        : "r"(a[0]), "r"(a[1]), "r"(a[2]), "r"(a[3]), "r"(b[0]), "r"(b[1]));
}

// smem: 4 tiles of 16KB in order AHI, ALO, BHI, BLO, then labels/table
#define OFF_AHI   0
#define OFF_ALO   16384
#define OFF_BHI   32768
#define OFF_BLO   49152
#define OFF_TBL   65536
#define OFF_STI   65792
#define OFF_STJ   66304
#define OFF_LABI  66816
#define OFF_LABJ  68864
#define SMEM_BYTES 70912

#define OFF_SRED1 0
#define OFF_SRED2 20480

// Chunk tile row layout: 128 rows x 128 bytes (64 bf16), 16B blocks XOR-swizzled.
__device__ __forceinline__ int sw_addr(int row, int c16) {
    return row * 128 + ((c16 ^ (row & 7)) << 4);
}

// One-pass fp32 -> bf16 hi/lo split into pre-swizzled chunked layout.
// Also detects the labels element stride (int64 vs int32).
__global__ __launch_bounds__(256) void split_kernel(
    const float* __restrict__ X, const int* __restrict__ labels)
{
    int idx = blockIdx.x * 256 + threadIdx.x;   // 0..131071
    int row = idx >> 5;
    int c8 = idx & 31;
    int chunk = c8 >> 4;
    int c8c = c8 & 15;
    float4 v = ((const float4*)X)[idx];
    unsigned hx = (unsigned)__bfloat16_as_ushort(__float2bfloat16(v.x));
    unsigned hy = (unsigned)__bfloat16_as_ushort(__float2bfloat16(v.y));
    unsigned hz = (unsigned)__bfloat16_as_ushort(__float2bfloat16(v.z));
    unsigned hw = (unsigned)__bfloat16_as_ushort(__float2bfloat16(v.w));
    float lx = v.x - __bfloat162float(__ushort_as_bfloat16((unsigned short)hx));
    float ly = v.y - __bfloat162float(__ushort_as_bfloat16((unsigned short)hy));
    float lz = v.z - __bfloat162float(__ushort_as_bfloat16((unsigned short)hz));
    float lw = v.w - __bfloat162float(__ushort_as_bfloat16((unsigned short)hw));
    uint2 hv;
    hv.x = hx | (hy << 16);
    hv.y = hz | (hw << 16);
    uint2 lv;
    lv.x = (unsigned)__bfloat16_as_ushort(__float2bfloat16(lx)) |
           ((unsigned)__bfloat16_as_ushort(__float2bfloat16(ly)) << 16);
    lv.y = (unsigned)__bfloat16_as_ushort(__float2bfloat16(lz)) |
           ((unsigned)__bfloat16_as_ushort(__float2bfloat16(lw)) << 16);
    u64 off = ((u64)(chunk * 4096 + row) << 7) +
              (u64)((((c8c >> 1) ^ (row & 7)) << 4) + ((c8c & 1) << 3));
    *(uint2*)(g_xhi + off) = hv;
    *(uint2*)(g_xlo + off) = lv;

    if (blockIdx.x == 0 && threadIdx.x < 32) {
        int lane = threadIdx.x;
        int lv2 = 0;
        if (lane < 16) lv2 = labels[2 * lane + 1];
        u32 m = __ballot_sync(0xffffffffu, lv2 != 0);
        if (lane == 0) g_estride = (m != 0) ? 1 : 2;
    }
}

__global__ __launch_bounds__(256, 2) void tile_kernel(
    const int* __restrict__ labels,
    float a0, float a1, float a2, float a3)
{
    extern __shared__ char smem[];
    const u32 sbase = smem_u32(smem);
    float4* tbl = (float4*)(smem + OFF_TBL);
    int* sTi = (int*)(smem + OFF_STI);
    int* sTj = (int*)(smem + OFF_STJ);
    int4* sLabI = (int4*)(smem + OFF_LABI);
    int4* sLabJ = (int4*)(smem + OFF_LABJ);

    const int tid = threadIdx.x;
    const int lane = tid & 31;
    const int wid = tid >> 5;
    const int wr = wid >> 2;
    const int wc = wid & 3;

    // decode block -> (bi, bj), off-diagonal pairs first, diagonals last
    int bi;
    int bj;
    if (blockIdx.x < NPAIR) {
        int rem = blockIdx.x;
        bi = 0;
        while (rem >= 31 - bi) {
            rem -= 31 - bi;
            bi++;
        }
        bj = bi + 1 + rem;
    } else {
        bi = blockIdx.x - NPAIR;
        bj = bi;
    }
    const int isdiag = (bi == bj) ? 1 : 0;
    const int ibase = bi * TS;
    const int jbase = bj * TS;
    const int es = g_estride;

    // ---- labels for both blocks + neg-pattern table ----
    if (tid < 128) {
        int gi = ibase + tid;
        sTi[tid] = labels[(gi * KK) * es];
        int4 lv4;
        lv4.x = labels[(gi * KK + 0) * es];
        lv4.y = labels[(gi * KK + 1) * es];
        lv4.z = labels[(gi * KK + 2) * es];
        lv4.w = labels[(gi * KK + 3) * es];
        sLabI[tid] = lv4;
        if (tid < 16) {
            int eb = tid;
            int e0 = eb & 1;
            int e1 = (eb >> 1) & 1;
            int e2 = (eb >> 2) & 1;
            int e3 = (eb >> 3) & 1;
            int n0 = 1 - e3;
            int n1 = (1 - e2) & e3;
            int n2 = (1 - e1) & e2;
            int n3 = (1 - e0) & e1;
            float kcnt = (float)(n0 + n1 + n2 + n3);
            float sa = n0 * a0 + n1 * a1 + n2 * a2 + n3 * a3;
            float sa2 = n0 * a0 * a0 + n1 * a1 * a1 + n2 * a2 * a2 + n3 * a3 * a3;
            tbl[eb] = make_float4(kcnt, sa, sa2, 0.0f);
        }
    } else {
        int r = tid - 128;
        int gj = jbase + r;
        sTj[r] = labels[(gj * KK) * es];
        int4 lv4;
        lv4.x = labels[(gj * KK + 0) * es];
        lv4.y = labels[(gj * KK + 1) * es];
        lv4.z = labels[(gj * KK + 2) * es];
        lv4.w = labels[(gj * KK + 3) * es];
        sLabJ[r] = lv4;
    }

    float acc[4][4][4];
    #pragma unroll
    for (int mt = 0; mt < 4; mt++)
        #pragma unroll
        for (int nt = 0; nt < 4; nt++)
            #pragma unroll
            for (int q = 0; q < 4; q++)
                acc[mt][nt][q] = 0.0f;

    const int a_row = lane & 15;
    const int a_k = lane >> 4;
    const int b_row = lane & 7;
    const int b_k = (lane >> 3) & 1;

    // ---- two K-chunks of 64: bulk-copy pre-split tiles, run 4 k-steps ----
    #pragma unroll
    for (int chunk = 0; chunk < 2; chunk++) {
        __syncthreads();   // previous chunk consumed (or labels phase done)

        #pragma unroll
        for (int tile = 0; tile < 4; tile++) {
            const unsigned char* src = ((tile & 1) != 0) ? g_xlo : g_xhi;
            int rb = (tile < 2) ? ibase : jbase;
            src += (u64)(chunk * 4096 + rb) << 7;
            u32 dst = sbase + tile * 16384;
            #pragma unroll
            for (int t = 0; t < 4; t++) {
                int woff = (t * 256 + tid) << 4;
                cp_async16(dst + woff, src + woff);
            }
        }
        cp_commit_wait0();
        __syncthreads();

        #pragma unroll
        for (int ks = 0; ks < 4; ks++) {
            u32 bh[4][2];
            u32 bl[4][2];
            int c16b = ks * 2 + b_k;
            #pragma unroll
            for (int nt = 0; nt < 4; nt++) {
                int r = wc * 32 + nt * 8 + b_row;
                u32 ad = (u32)sw_addr(r, c16b);
                ldsm_x2(bh[nt], sbase + OFF_BHI + ad);
                ldsm_x2(bl[nt], sbase + OFF_BLO + ad);
            }
            int c16a = ks * 2 + a_k;
            #pragma unroll
            for (int mt = 0; mt < 4; mt++) {
                int r = wr * 64 + mt * 16 + a_row;
                u32 ad = (u32)sw_addr(r, c16a);
                u32 ah[4];
                u32 al[4];
                ldsm_x4(ah, sbase + OFF_AHI + ad);
                ldsm_x4(al, sbase + OFF_ALO + ad);
                #pragma unroll
                for (int nt = 0; nt < 4; nt++) {
                    mma_bf16(acc[mt][nt], ah, bh[nt]);
                    mma_bf16(acc[mt][nt], ah, bl[nt]);
                    mma_bf16(acc[mt][nt], al, bh[nt]);
                }
            }
        }
    }

    __syncthreads();   // tile smem regions now free for reduce scratch

    // ---- convert acc -> log in place ----
    #pragma unroll
    for (int mt = 0; mt < 4; mt++)
        #pragma unroll
        for (int nt = 0; nt < 4; nt++)
            #pragma unroll
            for (int q = 0; q < 4; q++)
                acc[mt][nt][q] = __logf(acc[mt][nt][q] + EPSF);

    float* sred1 = (float*)(smem + OFF_SRED1);
    float* sred2 = (float*)(smem + OFF_SRED2);

    // ---- orientation 1: stats for i-block rows over j-block cols ----
    #pragma unroll
    for (int mt = 0; mt < 4; mt++) {
        #pragma unroll
        for (int h = 0; h < 2; h++) {
            int row = wr * 64 + mt * 16 + (lane >> 2) + h * 8;
            int tlab = sTi[row];
            int selfcol = (isdiag != 0) ? row : -1;
            float st[9];
            #pragma unroll
            for (int s = 0; s < 9; s++) st[s] = 0.0f;
            #pragma unroll
            for (int nt = 0; nt < 4; nt++) {
                #pragma unroll
                for (int e = 0; e < 2; e++) {
                    float L = acc[mt][nt][h * 2 + e];
                    float L2 = L * L;
                    int col = wc * 32 + nt * 8 + ((lane & 3) << 1) + e;
                    int4 lbv = sLabJ[col];
                    int p0 = (tlab == lbv.x) ? 1 : 0;
                    int eb = p0 | (((tlab == lbv.y) ? 1 : 0) << 1) |
                             (((tlab == lbv.z) ? 1 : 0) << 2) |
                             (((tlab == lbv.w) ? 1 : 0) << 3);
                    float4 tv = tbl[eb];
                    st[3] += tv.x;
                    st[4] += tv.y;
                    st[5] += tv.z;
                    st[6] = fmaf(tv.x, L, st[6]);
                    st[7] = fmaf(tv.y, L, st[7]);
                    st[8] = fmaf(tv.x, L2, st[8]);
                    if ((p0 != 0) && (col != selfcol)) {
                        st[0] += 1.0f;
                        st[1] += L;
                        st[2] += L2;
                    }
                }
            }
            #pragma unroll
            for (int s = 0; s < 9; s++) {
                float v = st[s];
                v += __shfl_xor_sync(0xffffffffu, v, 1);
                v += __shfl_xor_sync(0xffffffffu, v, 2);
                st[s] = v;
            }
            if ((lane & 3) == 0) {
                #pragma unroll
                for (int s = 0; s < 9; s++) sred1[(row * 4 + wc) * 9 + s] = st[s];
            }
        }
    }

    // ---- orientation 2 (off-diag only): stats for j-block rows over i-block cols ----
    if (isdiag == 0) {
        #pragma unroll
        for (int nt = 0; nt < 4; nt++) {
            #pragma unroll
            for (int e = 0; e < 2; e++) {
                int col = wc * 32 + nt * 8 + ((lane & 3) << 1) + e;
                int tlab2 = sTj[col];
                float st[9];
                #pragma unroll
                for (int s = 0; s < 9; s++) st[s] = 0.0f;
                #pragma unroll
                for (int mt = 0; mt < 4; mt++) {
                    #pragma unroll
                    for (int h = 0; h < 2; h++) {
                        float L = acc[mt][nt][h * 2 + e];
                        float L2 = L * L;
                        int row = wr * 64 + mt * 16 + (lane >> 2) + h * 8;
                        int4 lbv = sLabI[row];
                        int p0 = (tlab2 == lbv.x) ? 1 : 0;
                        int eb = p0 | (((tlab2 == lbv.y) ? 1 : 0) << 1) |
                                 (((tlab2 == lbv.z) ? 1 : 0) << 2) |
                                 (((tlab2 == lbv.w) ? 1 : 0) << 3);
                        float4 tv = tbl[eb];
                        st[3] += tv.x;
                        st[4] += tv.y;
                        st[5] += tv.z;
                        st[6] = fmaf(tv.x, L, st[6]);
                        st[7] = fmaf(tv.y, L, st[7]);
                        st[8] = fmaf(tv.x, L2, st[8]);
                        if (p0 != 0) {
                            st[0] += 1.0f;
                            st[1] += L;
                            st[2] += L2;
                        }
                    }
                }
                #pragma unroll
                for (int s = 0; s < 9; s++) {
                    float v = st[s];
                    v += __shfl_xor_sync(0xffffffffu, v, 4);
                    v += __shfl_xor_sync(0xffffffffu, v, 8);
                    v += __shfl_xor_sync(0xffffffffu, v, 16);
                    st[s] = v;
                }
                if ((lane >> 2) == 0) {
                    #pragma unroll
                    for (int s = 0; s < 9; s++) sred2[(col * 2 + wr) * 9 + s] = st[s];
                }
            }
        }
    }
    __syncthreads();

    // ---- final combines; coalesced write-once g_part [s][cb][row] ----
    if (tid < 128) {
        #pragma unroll
        for (int s = 0; s < 9; s++) {
            float v = sred1[(tid * 4 + 0) * 9 + s] + sred1[(tid * 4 + 1) * 9 + s] +
                      sred1[(tid * 4 + 2) * 9 + s] + sred1[(tid * 4 + 3) * 9 + s];
            g_part[(s * NBJ + bj) * N + ibase + tid] = v;
        }
    } else if (isdiag == 0) {
        int c2 = tid - 128;
        #pragma unroll
        for (int s = 0; s < 9; s++) {
            float v = sred2[(c2 * 2 + 0) * 9 + s] + sred2[(c2 * 2 + 1) * 9 + s];
            g_part[(s * NBJ + bi) * N + jbase + c2] = v;
        }
    }
}

// Combine: 64 blocks x 64 threads, one row per thread (fully coalesced),
// per-block tree, ticket finalize with parallel final reduce.
__global__ __launch_bounds__(64) void combine_kernel(float* __restrict__ out) {
    __shared__ float sh[CBLK];
    __shared__ u32 ticket_s;
    const int row = blockIdx.x * 64 + threadIdx.x;

    float agg[9];
    #pragma unroll
    for (int s = 0; s < 9; s++) {
        float v = 0.0f;
        #pragma unroll
        for (int cb = 0; cb < NBJ; cb++) {
            v += g_part[(s * NBJ + cb) * N + row];
        }
        agg[s] = v;
    }
    float rl = agg[2] * agg[3] - 2.0f * agg[1] * (agg[6] + agg[4])
             + agg[0] * (agg[8] + 2.0f * agg[7] + agg[5]);
    sh[threadIdx.x] = rl;
    __syncthreads();
    for (int o = 32; o > 0; o >>= 1) {
        if (threadIdx.x < (u32)o) sh[threadIdx.x] += sh[threadIdx.x + o];
        __syncthreads();
    }
    if (threadIdx.x == 0) {
        g_bsum[blockIdx.x] = sh[0];
        __threadfence();
        ticket_s = atomicAdd(&g_arrive, 1u);
    }
    __syncthreads();
    if (ticket_s == (CBLK - 1)) {
        __threadfence();
        float v = g_bsum[threadIdx.x];
        sh[threadIdx.x] = v;
        __syncthreads();
        for (int o = 32; o > 0; o >>= 1) {
            if (threadIdx.x < (u32)o) sh[threadIdx.x] += sh[threadIdx.x + o];
            __syncthreads();
        }
        if (threadIdx.x == 0) {
            out[0] = sh[0];
            g_arrive = 0;   // reset for next (graph-replayed) launch
        }
    }
}

extern "C" void kernel_launch(void* const* d_in, const int* in_sizes, int n_in,
                              void* d_out, int out_size) {
    (void)in_sizes; (void)n_in; (void)out_size;
    const float* X = (const float*)d_in[0];
    const int* labels = (const int*)d_in[1];
    float* out = (float*)d_out;

    const double lg = log(0.1 + 1e-6);
    float a[4];
    for (int m = 0; m < 4; m++) {
        a[m] = (float)(0.1 * (lg - log(pow(0.1, (double)(5 - m)) + 1e-6)));
    }

    cudaFuncSetAttribute(tile_kernel, cudaFuncAttributeMaxDynamicSharedMemorySize, SMEM_BYTES);

    split_kernel<<<512, 256>>>(X, labels);
    tile_kernel<<<NBLK, 256, SMEM_BYTES>>>(labels, a[0], a[1], a[2], a[3]);
    combine_kernel<<<CBLK, 64>>>(out);
}

// round 12
// speedup vs baseline: 5.8323x; 1.0395x over previous
#include <cuda_runtime.h>
#include <cuda_bf16.h>
#include <cstdint>
#include <math.h>

typedef unsigned int u32;
typedef unsigned long long u64;

#define N 4096
#define KK 4
#define TS 128
#define NBJ (N / TS)
#define NPAIR 496
#define NBLK 528
#define EPSF 1e-6f
#define CBLK 64

// g_part layout: [stat s][colblock cb][row]
__device__ float g_part[9 * NBJ * N];
__device__ float g_bsum[CBLK];
__device__ u32   g_arrive = 0;
__device__ int   g_estride;

// Pre-split, pre-swizzled bf16: [chunk(4)][row(4096)][64 bytes]
__device__ __align__(256) unsigned char g_xhi[4 * 4096 * 64];
__device__ __align__(256) unsigned char g_xlo[4 * 4096 * 64];

__device__ __forceinline__ u32 smem_u32(const void* p) {
    u32 a;
    asm("{ .reg .u64 t; cvta.to.shared.u64 t, %1; cvt.u32.u64 %0, t; }" : "=r"(a) : "l"(p));
    return a;
}

__device__ __forceinline__ void cp_async16(u32 smem_dst, const void* gsrc) {
    asm volatile("cp.async.cg.shared.global [%0], [%1], 16;"
                 :: "r"(smem_dst), "l"(gsrc) : "memory");
}

__device__ __forceinline__ void cp_commit() {
    asm volatile("cp.async.commit_group;" ::: "memory");
}

__device__ __forceinline__ void cp_wait1() {
    asm volatile("cp.async.wait_group 1;" ::: "memory");
}

__device__ __forceinline__ void cp_wait0() {
    asm volatile("cp.async.wait_group 0;" ::: "memory");
}

__device__ __forceinline__ void ldsm_x4(u32* r, u32 addr) {
    asm volatile("ldmatrix.sync.aligned.m8n8.x4.shared.b16 {%0,%1,%2,%3}, [%4];"
                 : "=r"(r[0]), "=r"(r[1]), "=r"(r[2]), "=r"(r[3]) : "r"(addr));
}

__device__ __forceinline__ void ldsm_x2(u32* r, u32 addr) {
    asm volatile("ldmatrix.sync.aligned.m8n8.x2.shared.b16 {%0,%1}, [%2];"
                 : "=r"(r[0]), "=r"(r[1]) : "r"(addr));
}

__device__ __forceinline__ void mma_bf16(float* c, const u32* a, const u32* b) {
    asm volatile(
        "mma.sync.aligned.m16n8k16.row.col.f32.bf16.bf16.f32 "
        "{%0,%1,%2,%3}, {%4,%5,%6,%7}, {%8,%9}, {%0,%1,%2,%3};"
        : "+f"(c[0]), "+f"(c[1]), "+f"(c[2]), "+f"(c[3])
        : "r"(a[0]), "r"(a[1]), "r"(a[2]), "r"(a[3]), "r"(b[0]), "r"(b[1]));
}

// smem: 2 chunk-set buffers of 32KB (tiles AHI,ALO,BHI,BLO at 8KB each), misc after
#define BUF_BYTES 32768
#define TILE_BYTES 8192
#define OFF_TBL   65536
#define OFF_STI   65792
#define OFF_STJ   66304
#define OFF_LABI  66816
#define OFF_LABJ  68864
#define SMEM_BYTES 70912

#define OFF_SRED1 0
#define OFF_SRED2 20480

// Chunk tile row layout: 128 rows x 64 bytes (32 bf16), 16B blocks XOR-swizzled.
__device__ __forceinline__ int sw_addr32(int row, int c16) {
    return row * 64 + (((c16 ^ (row >> 1)) & 3) << 4);
}

// One-pass fp32 -> bf16 hi/lo split into pre-swizzled chunked layout.
// Each thread: 2 float4 loads -> one 16B store per (hi, lo).
__global__ __launch_bounds__(256) void split_kernel(
    const float* __restrict__ X, const int* __restrict__ labels)
{
    int idx = blockIdx.x * 256 + threadIdx.x;   // 0..65535
    int row = idx >> 4;
    int c16p = idx & 15;                        // 16B-block index within the 128-col row
    int chunk = c16p >> 2;
    int c16 = c16p & 3;
    const float4* Xg = (const float4*)X;
    float4 v0 = Xg[row * 32 + c16p * 2];
    float4 v1 = Xg[row * 32 + c16p * 2 + 1];
    uint4 hv;
    uint4 lv;
    float vv[8];
    vv[0] = v0.x; vv[1] = v0.y; vv[2] = v0.z; vv[3] = v0.w;
    vv[4] = v1.x; vv[5] = v1.y; vv[6] = v1.z; vv[7] = v1.w;
    u32 hw[8];
    u32 lw[8];
    #pragma unroll
    for (int e = 0; e < 8; e++) {
        hw[e] = (u32)__bfloat16_as_ushort(__float2bfloat16(vv[e]));
        float lo = vv[e] - __bfloat162float(__ushort_as_bfloat16((unsigned short)hw[e]));
        lw[e] = (u32)__bfloat16_as_ushort(__float2bfloat16(lo));
    }
    hv.x = hw[0] | (hw[1] << 16);
    hv.y = hw[2] | (hw[3] << 16);
    hv.z = hw[4] | (hw[5] << 16);
    hv.w = hw[6] | (hw[7] << 16);
    lv.x = lw[0] | (lw[1] << 16);
    lv.y = lw[2] | (lw[3] << 16);
    lv.z = lw[4] | (lw[5] << 16);
    lv.w = lw[6] | (lw[7] << 16);
    u64 off = ((u64)(chunk * 4096 + row) << 6) + (u64)((((c16 ^ (row >> 1)) & 3)) << 4);
    *(uint4*)(g_xhi + off) = hv;
    *(uint4*)(g_xlo + off) = lv;

    if (blockIdx.x == 0 && threadIdx.x < 32) {
        int lane = threadIdx.x;
        int lv2 = 0;
        if (lane < 16) lv2 = labels[2 * lane + 1];
        u32 m = __ballot_sync(0xffffffffu, lv2 != 0);
        if (lane == 0) g_estride = (m != 0) ? 1 : 2;
    }
}

__global__ __launch_bounds__(256, 2) void tile_kernel(
    const int* __restrict__ labels,
    float a0, float a1, float a2, float a3)
{
    extern __shared__ char smem[];
    const u32 sbase = smem_u32(smem);
    float4* tbl = (float4*)(smem + OFF_TBL);
    int* sTi = (int*)(smem + OFF_STI);
    int* sTj = (int*)(smem + OFF_STJ);
    int4* sLabI = (int4*)(smem + OFF_LABI);
    int4* sLabJ = (int4*)(smem + OFF_LABJ);

    const int tid = threadIdx.x;
    const int lane = tid & 31;
    const int wid = tid >> 5;
    const int wr = wid >> 2;
    const int wc = wid & 3;

    int bi;
    int bj;
    if (blockIdx.x < NPAIR) {
        int rem = blockIdx.x;
        bi = 0;
        while (rem >= 31 - bi) {
            rem -= 31 - bi;
            bi++;
        }
        bj = bi + 1 + rem;
    } else {
        bi = blockIdx.x - NPAIR;
        bj = bi;
    }
    const int isdiag = (bi == bj) ? 1 : 0;
    const int ibase = bi * TS;
    const int jbase = bj * TS;
    const int es = g_estride;

    // ---- helper lambda-free chunk copy: issue 8 cp.async into buffer p ----
    // tiles: 0=AHI 1=ALO 2=BHI 3=BLO
    {
        // prefetch chunk 0 and 1
        #pragma unroll
        for (int c = 0; c < 2; c++) {
            u32 dst = sbase + c * BUF_BYTES;
            #pragma unroll
            for (int tile = 0; tile < 4; tile++) {
                const unsigned char* src = ((tile & 1) != 0) ? g_xlo : g_xhi;
                int rb = (tile < 2) ? ibase : jbase;
                src += (u64)(c * 4096 + rb) << 6;
                u32 d2 = dst + tile * TILE_BYTES;
                cp_async16(d2 + (tid << 4), src + (tid << 4));
                cp_async16(d2 + ((256 + tid) << 4), src + ((256 + tid) << 4));
            }
            cp_commit();
        }
    }

    // ---- labels for both blocks + neg-pattern table (overlaps cp.async) ----
    if (tid < 128) {
        int gi = ibase + tid;
        sTi[tid] = labels[(gi * KK) * es];
        int4 lv4;
        lv4.x = labels[(gi * KK + 0) * es];
        lv4.y = labels[(gi * KK + 1) * es];
        lv4.z = labels[(gi * KK + 2) * es];
        lv4.w = labels[(gi * KK + 3) * es];
        sLabI[tid] = lv4;
        if (tid < 16) {
            int eb = tid;
            int e0 = eb & 1;
            int e1 = (eb >> 1) & 1;
            int e2 = (eb >> 2) & 1;
            int e3 = (eb >> 3) & 1;
            int n0 = 1 - e3;
            int n1 = (1 - e2) & e3;
            int n2 = (1 - e1) & e2;
            int n3 = (1 - e0) & e1;
            float kcnt = (float)(n0 + n1 + n2 + n3);
            float sa = n0 * a0 + n1 * a1 + n2 * a2 + n3 * a3;
            float sa2 = n0 * a0 * a0 + n1 * a1 * a1 + n2 * a2 * a2 + n3 * a3 * a3;
            tbl[eb] = make_float4(kcnt, sa, sa2, 0.0f);
        }
    } else {
        int r = tid - 128;
        int gj = jbase + r;
        sTj[r] = labels[(gj * KK) * es];
        int4 lv4;
        lv4.x = labels[(gj * KK + 0) * es];
        lv4.y = labels[(gj * KK + 1) * es];
        lv4.z = labels[(gj * KK + 2) * es];
        lv4.w = labels[(gj * KK + 3) * es];
        sLabJ[r] = lv4;
    }

    float acc[4][4][4];
    #pragma unroll
    for (int mt = 0; mt < 4; mt++)
        #pragma unroll
        for (int nt = 0; nt < 4; nt++)
            #pragma unroll
            for (int q = 0; q < 4; q++)
                acc[mt][nt][q] = 0.0f;

    const int a_row = lane & 15;
    const int a_k = lane >> 4;
    const int b_row = lane & 7;
    const int b_k = (lane >> 3) & 1;

    // ---- pipelined mainloop: 4 chunks of K=32, double-buffered ----
    #pragma unroll
    for (int c = 0; c < 4; c++) {
        if (c < 3) {
            cp_wait1();
        } else {
            cp_wait0();
        }
        __syncthreads();   // buffer c%2 fully arrived for all threads

        const u32 buf = sbase + (u32)(c & 1) * BUF_BYTES;
        #pragma unroll
        for (int ks = 0; ks < 2; ks++) {
            u32 bh[4][2];
            u32 bl[4][2];
            int c16b = ks * 2 + b_k;
            #pragma unroll
            for (int nt = 0; nt < 4; nt++) {
                int r = wc * 32 + nt * 8 + b_row;
                u32 ad = (u32)sw_addr32(r, c16b);
                ldsm_x2(bh[nt], buf + 2 * TILE_BYTES + ad);
                ldsm_x2(bl[nt], buf + 3 * TILE_BYTES + ad);
            }
            int c16a = ks * 2 + a_k;
            #pragma unroll
            for (int mt = 0; mt < 4; mt++) {
                int r = wr * 64 + mt * 16 + a_row;
                u32 ad = (u32)sw_addr32(r, c16a);
                u32 ah[4];
                u32 al[4];
                ldsm_x4(ah, buf + ad);
                ldsm_x4(al, buf + TILE_BYTES + ad);
                #pragma unroll
                for (int nt = 0; nt < 4; nt++) {
                    mma_bf16(acc[mt][nt], ah, bh[nt]);
                    mma_bf16(acc[mt][nt], ah, bl[nt]);
                    mma_bf16(acc[mt][nt], al, bh[nt]);
                }
            }
        }
        __syncthreads();   // all warps done reading buffer c%2

        if (c < 2) {
            // refill the buffer just consumed with chunk c+2
            u32 dst = sbase + (u32)(c & 1) * BUF_BYTES;
            #pragma unroll
            for (int tile = 0; tile < 4; tile++) {
                const unsigned char* src = ((tile & 1) != 0) ? g_xlo : g_xhi;
                int rb = (tile < 2) ? ibase : jbase;
                src += (u64)((c + 2) * 4096 + rb) << 6;
                u32 d2 = dst + tile * TILE_BYTES;
                cp_async16(d2 + (tid << 4), src + (tid << 4));
                cp_async16(d2 + ((256 + tid) << 4), src + ((256 + tid) << 4));
            }
            cp_commit();
        }
    }

    // ---- convert acc -> log in place ----
    #pragma unroll
    for (int mt = 0; mt < 4; mt++)
        #pragma unroll
        for (int nt = 0; nt < 4; nt++)
            #pragma unroll
            for (int q = 0; q < 4; q++)
                acc[mt][nt][q] = __logf(acc[mt][nt][q] + EPSF);

    float* sred1 = (float*)(smem + OFF_SRED1);
    float* sred2 = (float*)(smem + OFF_SRED2);

    // ---- orientation 1 ----
    #pragma unroll
    for (int mt = 0; mt < 4; mt++) {
        #pragma unroll
        for (int h = 0; h < 2; h++) {
            int row = wr * 64 + mt * 16 + (lane >> 2) + h * 8;
            int tlab = sTi[row];
            int selfcol = (isdiag != 0) ? row : -1;
            float st[9];
            #pragma unroll
            for (int s = 0; s < 9; s++) st[s] = 0.0f;
            #pragma unroll
            for (int nt = 0; nt < 4; nt++) {
                #pragma unroll
                for (int e = 0; e < 2; e++) {
                    float L = acc[mt][nt][h * 2 + e];
                    float L2 = L * L;
                    int col = wc * 32 + nt * 8 + ((lane & 3) << 1) + e;
                    int4 lbv = sLabJ[col];
                    int p0 = (tlab == lbv.x) ? 1 : 0;
                    int eb = p0 | (((tlab == lbv.y) ? 1 : 0) << 1) |
                             (((tlab == lbv.z) ? 1 : 0) << 2) |
                             (((tlab == lbv.w) ? 1 : 0) << 3);
                    float4 tv = tbl[eb];
                    st[3] += tv.x;
                    st[4] += tv.y;
                    st[5] += tv.z;
                    st[6] = fmaf(tv.x, L, st[6]);
                    st[7] = fmaf(tv.y, L, st[7]);
                    st[8] = fmaf(tv.x, L2, st[8]);
                    if ((p0 != 0) && (col != selfcol)) {
                        st[0] += 1.0f;
                        st[1] += L;
                        st[2] += L2;
                    }
                }
            }
            #pragma unroll
            for (int s = 0; s < 9; s++) {
                float v = st[s];
                v += __shfl_xor_sync(0xffffffffu, v, 1);
                v += __shfl_xor_sync(0xffffffffu, v, 2);
                st[s] = v;
            }
            if ((lane & 3) == 0) {
                #pragma unroll
                for (int s = 0; s < 9; s++) sred1[(row * 4 + wc) * 9 + s] = st[s];
            }
        }
    }

    // ---- orientation 2 (off-diag only) ----
    if (isdiag == 0) {
        #pragma unroll
        for (int nt = 0; nt < 4; nt++) {
            #pragma unroll
            for (int e = 0; e < 2; e++) {
                int col = wc * 32 + nt * 8 + ((lane & 3) << 1) + e;
                int tlab2 = sTj[col];
                float st[9];
                #pragma unroll
                for (int s = 0; s < 9; s++) st[s] = 0.0f;
                #pragma unroll
                for (int mt = 0; mt < 4; mt++) {
                    #pragma unroll
                    for (int h = 0; h < 2; h++) {
                        float L = acc[mt][nt][h * 2 + e];
                        float L2 = L * L;
                        int row = wr * 64 + mt * 16 + (lane >> 2) + h * 8;
                        int4 lbv = sLabI[row];
                        int p0 = (tlab2 == lbv.x) ? 1 : 0;
                        int eb = p0 | (((tlab2 == lbv.y) ? 1 : 0) << 1) |
                                 (((tlab2 == lbv.z) ? 1 : 0) << 2) |
                                 (((tlab2 == lbv.w) ? 1 : 0) << 3);
                        float4 tv = tbl[eb];
                        st[3] += tv.x;
                        st[4] += tv.y;
                        st[5] += tv.z;
                        st[6] = fmaf(tv.x, L, st[6]);
                        st[7] = fmaf(tv.y, L, st[7]);
                        st[8] = fmaf(tv.x, L2, st[8]);
                        if (p0 != 0) {
                            st[0] += 1.0f;
                            st[1] += L;
                            st[2] += L2;
                        }
                    }
                }
                #pragma unroll
                for (int s = 0; s < 9; s++) {
                    float v = st[s];
                    v += __shfl_xor_sync(0xffffffffu, v, 4);
                    v += __shfl_xor_sync(0xffffffffu, v, 8);
                    v += __shfl_xor_sync(0xffffffffu, v, 16);
                    st[s] = v;
                }
                if ((lane >> 2) == 0) {
                    #pragma unroll
                    for (int s = 0; s < 9; s++) sred2[(col * 2 + wr) * 9 + s] = st[s];
                }
            }
        }
    }
    __syncthreads();

    if (tid < 128) {
        #pragma unroll
        for (int s = 0; s < 9; s++) {
            float v = sred1[(tid * 4 + 0) * 9 + s] + sred1[(tid * 4 + 1) * 9 + s] +
                      sred1[(tid * 4 + 2) * 9 + s] + sred1[(tid * 4 + 3) * 9 + s];
            g_part[(s * NBJ + bj) * N + ibase + tid] = v;
        }
    } else if (isdiag == 0) {
        int c2 = tid - 128;
        #pragma unroll
        for (int s = 0; s < 9; s++) {
            float v = sred2[(c2 * 2 + 0) * 9 + s] + sred2[(c2 * 2 + 1) * 9 + s];
            g_part[(s * NBJ + bi) * N + jbase + c2] = v;
        }
    }
}

__global__ __launch_bounds__(64) void combine_kernel(float* __restrict__ out) {
    __shared__ float sh[CBLK];
    __shared__ u32 ticket_s;
    const int row = blockIdx.x * 64 + threadIdx.x;

    float agg[9];
    #pragma unroll
    for (int s = 0; s < 9; s++) {
        float v = 0.0f;
        #pragma unroll
        for (int cb = 0; cb < NBJ; cb++) {
            v += g_part[(s * NBJ + cb) * N + row];
        }
        agg[s] = v;
    }
    float rl = agg[2] * agg[3] - 2.0f * agg[1] * (agg[6] + agg[4])
             + agg[0] * (agg[8] + 2.0f * agg[7] + agg[5]);
    sh[threadIdx.x] = rl;
    __syncthreads();
    for (int o = 32; o > 0; o >>= 1) {
        if (threadIdx.x < (u32)o) sh[threadIdx.x] += sh[threadIdx.x + o];
        __syncthreads();
    }
    if (threadIdx.x == 0) {
        g_bsum[blockIdx.x] = sh[0];
        __threadfence();
        ticket_s = atomicAdd(&g_arrive, 1u);
    }
    __syncthreads();
    if (ticket_s == (CBLK - 1)) {
        __threadfence();
        float v = g_bsum[threadIdx.x];
        sh[threadIdx.x] = v;
        __syncthreads();
        for (int o = 32; o > 0; o >>= 1) {
            if (threadIdx.x < (u32)o) sh[threadIdx.x] += sh[threadIdx.x + o];
            __syncthreads();
        }
        if (threadIdx.x == 0) {
            out[0] = sh[0];
            g_arrive = 0;
        }
    }
}

extern "C" void kernel_launch(void* const* d_in, const int* in_sizes, int n_in,
                              void* d_out, int out_size) {
    (void)in_sizes; (void)n_in; (void)out_size;
    const float* X = (const float*)d_in[0];
    const int* labels = (const int*)d_in[1];
    float* out = (float*)d_out;

    const double lg = log(0.1 + 1e-6);
    float a[4];
    for (int m = 0; m < 4; m++) {
        a[m] = (float)(0.1 * (lg - log(pow(0.1, (double)(5 - m)) + 1e-6)));
    }

    cudaFuncSetAttribute(tile_kernel, cudaFuncAttributeMaxDynamicSharedMemorySize, SMEM_BYTES);

    split_kernel<<<256, 256>>>(X, labels);
    tile_kernel<<<NBLK, 256, SMEM_BYTES>>>(labels, a[0], a[1], a[2], a[3]);
    combine_kernel<<<CBLK, 64>>>(out);
}

// round 13
// speedup vs baseline: 6.5778x; 1.1278x over previous
#include <cuda_runtime.h>
#include <cuda_fp16.h>
#include <cstdint>
#include <math.h>

typedef unsigned int u32;
typedef unsigned long long u64;

#define N 4096
#define KK 4
#define TS 128
#define NBJ (N / TS)
#define NPAIR 496
#define NBLK 528
#define EPSF 1e-6f
#define CBLK 64

// g_part layout: [stat s][colblock cb][row]
__device__ float g_part[9 * NBJ * N];
__device__ float g_bsum[CBLK];
__device__ u32   g_arrive = 0;
__device__ int   g_estride;

// Pre-split, pre-swizzled fp16: [row(4096)][256 bytes]
__device__ __align__(256) unsigned char g_xf16[4096 * 256];

__device__ __forceinline__ u32 smem_u32(const void* p) {
    u32 a;
    asm("{ .reg .u64 t; cvta.to.shared.u64 t, %1; cvt.u32.u64 %0, t; }" : "=r"(a) : "l"(p));
    return a;
}

__device__ __forceinline__ void cp_async16(u32 smem_dst, const void* gsrc) {
    asm volatile("cp.async.cg.shared.global [%0], [%1], 16;"
                 :: "r"(smem_dst), "l"(gsrc) : "memory");
}

__device__ __forceinline__ void cp_commit_wait0() {
    asm volatile("cp.async.commit_group;" ::: "memory");
    asm volatile("cp.async.wait_group 0;" ::: "memory");
}

__device__ __forceinline__ void ldsm_x4(u32* r, u32 addr) {
    asm volatile("ldmatrix.sync.aligned.m8n8.x4.shared.b16 {%0,%1,%2,%3}, [%4];"
                 : "=r"(r[0]), "=r"(r[1]), "=r"(r[2]), "=r"(r[3]) : "r"(addr));
}

__device__ __forceinline__ void ldsm_x2(u32* r, u32 addr) {
    asm volatile("ldmatrix.sync.aligned.m8n8.x2.shared.b16 {%0,%1}, [%2];"
                 : "=r"(r[0]), "=r"(r[1]) : "r"(addr));
}

__device__ __forceinline__ void mma_f16(float* c, const u32* a, const u32* b) {
    asm volatile(
        "mma.sync.aligned.m16n8k16.row.col.f32.f16.f16.f32 "
        "{%0,%1,%2,%3}, {%4,%5,%6,%7}, {%8,%9}, {%0,%1,%2,%3};"
        : "+f"(c[0]), "+f"(c[1]), "+f"(c[2]), "+f"(c[3])
        : "r"(a[0]), "r"(a[1]), "r"(a[2]), "r"(a[3]), "r"(b[0]), "r"(b[1]));
}

// smem: A tile 32KB at 0, B tile 32KB at 32768, misc after
#define OFF_A     0
#define OFF_B     32768
#define OFF_TBL   65536
#define OFF_STI   65792
#define OFF_STJ   66304
#define OFF_LABI  66816
#define OFF_LABJ  68864
#define SMEM_BYTES 70912

#define OFF_SRED1 0
#define OFF_SRED2 20480

// Tile row layout: 128 rows x 256 bytes (128 fp16), 16B blocks XOR-swizzled.
__device__ __forceinline__ int sw_addr(int row, int c16) {
    return row * 256 + ((c16 ^ (row & 7)) << 4);
}

// One-pass fp32 -> fp16 into pre-swizzled layout. Each thread: 8 floats -> 16B.
__global__ __launch_bounds__(256) void split_kernel(
    const float* __restrict__ X, const int* __restrict__ labels)
{
    int idx = blockIdx.x * 256 + threadIdx.x;   // 0..65535
    int row = idx >> 4;
    int c16 = idx & 15;
    const float4* Xg = (const float4*)X;
    float4 v0 = Xg[row * 32 + c16 * 2];
    float4 v1 = Xg[row * 32 + c16 * 2 + 1];
    float vv[8];
    vv[0] = v0.x; vv[1] = v0.y; vv[2] = v0.z; vv[3] = v0.w;
    vv[4] = v1.x; vv[5] = v1.y; vv[6] = v1.z; vv[7] = v1.w;
    u32 hw[8];
    #pragma unroll
    for (int e = 0; e < 8; e++) {
        hw[e] = (u32)__half_as_ushort(__float2half_rn(vv[e]));
    }
    uint4 hv;
    hv.x = hw[0] | (hw[1] << 16);
    hv.y = hw[2] | (hw[3] << 16);
    hv.z = hw[4] | (hw[5] << 16);
    hv.w = hw[6] | (hw[7] << 16);
    u64 off = ((u64)row << 8) + (u64)(((c16 ^ (row & 7))) << 4);
    *(uint4*)(g_xf16 + off) = hv;

    if (blockIdx.x == 0 && threadIdx.x < 32) {
        int lane = threadIdx.x;
        int lv2 = 0;
        if (lane < 16) lv2 = labels[2 * lane + 1];
        u32 m = __ballot_sync(0xffffffffu, lv2 != 0);
        if (lane == 0) g_estride = (m != 0) ? 1 : 2;
    }
}

__global__ __launch_bounds__(256, 2) void tile_kernel(
    const int* __restrict__ labels,
    float a0, float a1, float a2, float a3)
{
    extern __shared__ char smem[];
    const u32 sbase = smem_u32(smem);
    float4* tbl = (float4*)(smem + OFF_TBL);
    int* sTi = (int*)(smem + OFF_STI);
    int* sTj = (int*)(smem + OFF_STJ);
    int4* sLabI = (int4*)(smem + OFF_LABI);
    int4* sLabJ = (int4*)(smem + OFF_LABJ);

    const int tid = threadIdx.x;
    const int lane = tid & 31;
    const int wid = tid >> 5;
    const int wr = wid >> 2;
    const int wc = wid & 3;

    int bi;
    int bj;
    if (blockIdx.x < NPAIR) {
        int rem = blockIdx.x;
        bi = 0;
        while (rem >= 31 - bi) {
            rem -= 31 - bi;
            bi++;
        }
        bj = bi + 1 + rem;
    } else {
        bi = blockIdx.x - NPAIR;
        bj = bi;
    }
    const int isdiag = (bi == bj) ? 1 : 0;
    const int ibase = bi * TS;
    const int jbase = bj * TS;
    const int es = g_estride;

    // ---- bulk-copy both pre-swizzled tiles (A: i-block, B: j-block) ----
    {
        const unsigned char* srcA = g_xf16 + ((u64)ibase << 8);
        const unsigned char* srcB = g_xf16 + ((u64)jbase << 8);
        #pragma unroll
        for (int t = 0; t < 8; t++) {
            int woff = (t * 256 + tid) << 4;
            cp_async16(sbase + OFF_A + woff, srcA + woff);
            cp_async16(sbase + OFF_B + woff, srcB + woff);
        }
    }

    // ---- labels for both blocks + neg-pattern table (overlaps cp.async) ----
    if (tid < 128) {
        int gi = ibase + tid;
        sTi[tid] = labels[(gi * KK) * es];
        int4 lv4;
        lv4.x = labels[(gi * KK + 0) * es];
        lv4.y = labels[(gi * KK + 1) * es];
        lv4.z = labels[(gi * KK + 2) * es];
        lv4.w = labels[(gi * KK + 3) * es];
        sLabI[tid] = lv4;
        if (tid < 16) {
            int eb = tid;
            int e0 = eb & 1;
            int e1 = (eb >> 1) & 1;
            int e2 = (eb >> 2) & 1;
            int e3 = (eb >> 3) & 1;
            int n0 = 1 - e3;
            int n1 = (1 - e2) & e3;
            int n2 = (1 - e1) & e2;
            int n3 = (1 - e0) & e1;
            float kcnt = (float)(n0 + n1 + n2 + n3);
            float sa = n0 * a0 + n1 * a1 + n2 * a2 + n3 * a3;
            float sa2 = n0 * a0 * a0 + n1 * a1 * a1 + n2 * a2 * a2 + n3 * a3 * a3;
            tbl[eb] = make_float4(kcnt, sa, sa2, 0.0f);
        }
    } else {
        int r = tid - 128;
        int gj = jbase + r;
        sTj[r] = labels[(gj * KK) * es];
        int4 lv4;
        lv4.x = labels[(gj * KK + 0) * es];
        lv4.y = labels[(gj * KK + 1) * es];
        lv4.z = labels[(gj * KK + 2) * es];
        lv4.w = labels[(gj * KK + 3) * es];
        sLabJ[r] = lv4;
    }

    float acc[4][4][4];
    #pragma unroll
    for (int mt = 0; mt < 4; mt++)
        #pragma unroll
        for (int nt = 0; nt < 4; nt++)
            #pragma unroll
            for (int q = 0; q < 4; q++)
                acc[mt][nt][q] = 0.0f;

    const int a_row = lane & 15;
    const int a_k = lane >> 4;
    const int b_row = lane & 7;
    const int b_k = (lane >> 3) & 1;

    cp_commit_wait0();
    __syncthreads();

    // ---- single fp16 GEMM: 8 k-steps x 16 mma ----
    #pragma unroll
    for (int ks = 0; ks < 8; ks++) {
        u32 bh[4][2];
        int c16b = ks * 2 + b_k;
        #pragma unroll
        for (int nt = 0; nt < 4; nt++) {
            int r = wc * 32 + nt * 8 + b_row;
            ldsm_x2(bh[nt], sbase + OFF_B + (u32)sw_addr(r, c16b));
        }
        int c16a = ks * 2 + a_k;
        #pragma unroll
        for (int mt = 0; mt < 4; mt++) {
            int r = wr * 64 + mt * 16 + a_row;
            u32 ah[4];
            ldsm_x4(ah, sbase + OFF_A + (u32)sw_addr(r, c16a));
            #pragma unroll
            for (int nt = 0; nt < 4; nt++) {
                mma_f16(acc[mt][nt], ah, bh[nt]);
            }
        }
    }

    __syncthreads();   // tile smem now free for reduce scratch

    // ---- convert acc -> log in place ----
    #pragma unroll
    for (int mt = 0; mt < 4; mt++)
        #pragma unroll
        for (int nt = 0; nt < 4; nt++)
            #pragma unroll
            for (int q = 0; q < 4; q++)
                acc[mt][nt][q] = __logf(acc[mt][nt][q] + EPSF);

    float* sred1 = (float*)(smem + OFF_SRED1);
    float* sred2 = (float*)(smem + OFF_SRED2);

    // ---- orientation 1: stats for i-block rows over j-block cols ----
    #pragma unroll
    for (int mt = 0; mt < 4; mt++) {
        #pragma unroll
        for (int h = 0; h < 2; h++) {
            int row = wr * 64 + mt * 16 + (lane >> 2) + h * 8;
            int tlab = sTi[row];
            int selfcol = (isdiag != 0) ? row : -1;
            float st[9];
            #pragma unroll
            for (int s = 0; s < 9; s++) st[s] = 0.0f;
            #pragma unroll
            for (int nt = 0; nt < 4; nt++) {
                #pragma unroll
                for (int e = 0; e < 2; e++) {
                    float L = acc[mt][nt][h * 2 + e];
                    float L2 = L * L;
                    int col = wc * 32 + nt * 8 + ((lane & 3) << 1) + e;
                    int4 lbv = sLabJ[col];
                    int p0 = (tlab == lbv.x) ? 1 : 0;
                    int eb = p0 | (((tlab == lbv.y) ? 1 : 0) << 1) |
                             (((tlab == lbv.z) ? 1 : 0) << 2) |
                             (((tlab == lbv.w) ? 1 : 0) << 3);
                    float4 tv = tbl[eb];
                    st[3] += tv.x;
                    st[4] += tv.y;
                    st[5] += tv.z;
                    st[6] = fmaf(tv.x, L, st[6]);
                    st[7] = fmaf(tv.y, L, st[7]);
                    st[8] = fmaf(tv.x, L2, st[8]);
                    if ((p0 != 0) && (col != selfcol)) {
                        st[0] += 1.0f;
                        st[1] += L;
                        st[2] += L2;
                    }
                }
            }
            #pragma unroll
            for (int s = 0; s < 9; s++) {
                float v = st[s];
                v += __shfl_xor_sync(0xffffffffu, v, 1);
                v += __shfl_xor_sync(0xffffffffu, v, 2);
                st[s] = v;
            }
            if ((lane & 3) == 0) {
                #pragma unroll
                for (int s = 0; s < 9; s++) sred1[(row * 4 + wc) * 9 + s] = st[s];
            }
        }
    }

    // ---- orientation 2 (off-diag only) ----
    if (isdiag == 0) {
        #pragma unroll
        for (int nt = 0; nt < 4; nt++) {
            #pragma unroll
            for (int e = 0; e < 2; e++) {
                int col = wc * 32 + nt * 8 + ((lane & 3) << 1) + e;
                int tlab2 = sTj[col];
                float st[9];
                #pragma unroll
                for (int s = 0; s < 9; s++) st[s] = 0.0f;
                #pragma unroll
                for (int mt = 0; mt < 4; mt++) {
                    #pragma unroll
                    for (int h = 0; h < 2; h++) {
                        float L = acc[mt][nt][h * 2 + e];
                        float L2 = L * L;
                        int row = wr * 64 + mt * 16 + (lane >> 2) + h * 8;
                        int4 lbv = sLabI[row];
                        int p0 = (tlab2 == lbv.x) ? 1 : 0;
                        int eb = p0 | (((tlab2 == lbv.y) ? 1 : 0) << 1) |
                                 (((tlab2 == lbv.z) ? 1 : 0) << 2) |
                                 (((tlab2 == lbv.w) ? 1 : 0) << 3);
                        float4 tv = tbl[eb];
                        st[3] += tv.x;
                        st[4] += tv.y;
                        st[5] += tv.z;
                        st[6] = fmaf(tv.x, L, st[6]);
                        st[7] = fmaf(tv.y, L, st[7]);
                        st[8] = fmaf(tv.x, L2, st[8]);
                        if (p0 != 0) {
                            st[0] += 1.0f;
                            st[1] += L;
                            st[2] += L2;
                        }
                    }
                }
                #pragma unroll
                for (int s = 0; s < 9; s++) {
                    float v = st[s];
                    v += __shfl_xor_sync(0xffffffffu, v, 4);
                    v += __shfl_xor_sync(0xffffffffu, v, 8);
                    v += __shfl_xor_sync(0xffffffffu, v, 16);
                    st[s] = v;
                }
                if ((lane >> 2) == 0) {
                    #pragma unroll
                    for (int s = 0; s < 9; s++) sred2[(col * 2 + wr) * 9 + s] = st[s];
                }
            }
        }
    }
    __syncthreads();

    if (tid < 128) {
        #pragma unroll
        for (int s = 0; s < 9; s++) {
            float v = sred1[(tid * 4 + 0) * 9 + s] + sred1[(tid * 4 + 1) * 9 + s] +
                      sred1[(tid * 4 + 2) * 9 + s] + sred1[(tid * 4 + 3) * 9 + s];
            g_part[(s * NBJ + bj) * N + ibase + tid] = v;
        }
    } else if (isdiag == 0) {
        int c2 = tid - 128;
        #pragma unroll
        for (int s = 0; s < 9; s++) {
            float v = sred2[(c2 * 2 + 0) * 9 + s] + sred2[(c2 * 2 + 1) * 9 + s];
            g_part[(s * NBJ + bi) * N + jbase + c2] = v;
        }
    }
}

__global__ __launch_bounds__(64) void combine_kernel(float* __restrict__ out) {
    __shared__ float sh[CBLK];
    __shared__ u32 ticket_s;
    const int row = blockIdx.x * 64 + threadIdx.x;

    float agg[9];
    #pragma unroll
    for (int s = 0; s < 9; s++) {
        float v = 0.0f;
        #pragma unroll
        for (int cb = 0; cb < NBJ; cb++) {
            v += g_part[(s * NBJ + cb) * N + row];
        }
        agg[s] = v;
    }
    float rl = agg[2] * agg[3] - 2.0f * agg[1] * (agg[6] + agg[4])
             + agg[0] * (agg[8] + 2.0f * agg[7] + agg[5]);
    sh[threadIdx.x] = rl;
    __syncthreads();
    for (int o = 32; o > 0; o >>= 1) {
        if (threadIdx.x < (u32)o) sh[threadIdx.x] += sh[threadIdx.x + o];
        __syncthreads();
    }
    if (threadIdx.x == 0) {
        g_bsum[blockIdx.x] = sh[0];
        __threadfence();
        ticket_s = atomicAdd(&g_arrive, 1u);
    }
    __syncthreads();
    if (ticket_s == (CBLK - 1)) {
        __threadfence();
        float v = g_bsum[threadIdx.x];
        sh[threadIdx.x] = v;
        __syncthreads();
        for (int o = 32; o > 0; o >>= 1) {
            if (threadIdx.x < (u32)o) sh[threadIdx.x] += sh[threadIdx.x + o];
            __syncthreads();
        }
        if (threadIdx.x == 0) {
            out[0] = sh[0];
            g_arrive = 0;
        }
    }
}

extern "C" void kernel_launch(void* const* d_in, const int* in_sizes, int n_in,
                              void* d_out, int out_size) {
    (void)in_sizes; (void)n_in; (void)out_size;
    const float* X = (const float*)d_in[0];
    const int* labels = (const int*)d_in[1];
    float* out = (float*)d_out;

    const double lg = log(0.1 + 1e-6);
    float a[4];
    for (int m = 0; m < 4; m++) {
        a[m] = (float)(0.1 * (lg - log(pow(0.1, (double)(5 - m)) + 1e-6)));
    }

    cudaFuncSetAttribute(tile_kernel, cudaFuncAttributeMaxDynamicSharedMemorySize, SMEM_BYTES);

    split_kernel<<<256, 256>>>(X, labels);
    tile_kernel<<<NBLK, 256, SMEM_BYTES>>>(labels, a[0], a[1], a[2], a[3]);
    combine_kernel<<<CBLK, 64>>>(out);
}